// round 7
// baseline (speedup 1.0000x reference)
#include <cuda_runtime.h>
#include <cuda_bf16.h>
#include <cstdint>

// ---------------- problem constants ----------------
#define Bb   64
#define Tt   512
#define Ee   256
#define Hh   256
#define G4   1024          // 4*H
#define Oo   2

// ---------------- scratch (device globals: no runtime alloc) ----------------
__device__ float g_xproj[(size_t)Tt * Bb * G4];   // [t][b][gate] fp32, 128MB
__device__ float g_hf[Bb * Hh];                   // final forward hidden

__device__ __forceinline__ float sigm(float x) {
    return __fdividef(1.0f, 1.0f + __expf(-x));
}
__device__ __forceinline__ float tanh_fast(float x) {
    return __fdividef(2.0f, 1.0f + __expf(-2.0f * x)) - 1.0f;
}

// =====================================================================
// Kernel 1: xproj = emb[x] @ W_ih_f^T + (b_ih_f + b_hh_f)
// (round-4 known-good version, 413us)
// =====================================================================
#define BM 128
#define BN 128
#define BK 8
__global__ __launch_bounds__(256) void xproj_kernel(
    const int* __restrict__ x,
    const float* __restrict__ emb,
    const float* __restrict__ wih,
    const float* __restrict__ bih,
    const float* __restrict__ bhh)
{
    __shared__ float As[BK][BM];
    __shared__ float Bs[BK][BN];

    const int bm = blockIdx.x;
    const int bn = blockIdx.y;
    const int tid = threadIdx.x;
    const int tx = tid & 15, ty = tid >> 4;

    const int arow = tid >> 1;
    const int ac4  = (tid & 1) * 4;
    const int m    = bm * BM + arow;
    const int bb   = m & 63;
    const int tt   = m >> 6;
    const int tok  = x[bb * Tt + tt];
    const float* aptr = emb + (size_t)tok * Ee;

    const int brow = tid >> 1;
    const int bc4  = (tid & 1) * 4;
    const float* bptr = wih + (size_t)(bn * BN + brow) * Ee;

    float acc[8][8];
#pragma unroll
    for (int i = 0; i < 8; i++)
#pragma unroll
        for (int j = 0; j < 8; j++) acc[i][j] = 0.0f;

    for (int k0 = 0; k0 < Ee; k0 += BK) {
        float4 av = *(const float4*)(aptr + k0 + ac4);
        float4 bv = *(const float4*)(bptr + k0 + bc4);
        __syncthreads();
        As[ac4 + 0][arow] = av.x; As[ac4 + 1][arow] = av.y;
        As[ac4 + 2][arow] = av.z; As[ac4 + 3][arow] = av.w;
        Bs[bc4 + 0][brow] = bv.x; Bs[bc4 + 1][brow] = bv.y;
        Bs[bc4 + 2][brow] = bv.z; Bs[bc4 + 3][brow] = bv.w;
        __syncthreads();
#pragma unroll
        for (int k = 0; k < BK; k++) {
            float a[8], b[8];
#pragma unroll
            for (int i = 0; i < 8; i += 4) {
                float4 v = *(const float4*)&As[k][ty * 8 + i];
                a[i] = v.x; a[i + 1] = v.y; a[i + 2] = v.z; a[i + 3] = v.w;
            }
#pragma unroll
            for (int j = 0; j < 8; j += 4) {
                float4 v = *(const float4*)&Bs[k][tx * 8 + j];
                b[j] = v.x; b[j + 1] = v.y; b[j + 2] = v.z; b[j + 3] = v.w;
            }
#pragma unroll
            for (int i = 0; i < 8; i++)
#pragma unroll
                for (int j = 0; j < 8; j++)
                    acc[i][j] = fmaf(a[i], b[j], acc[i][j]);
        }
    }

    const int gm = bm * BM + ty * 8;
    const int gn = bn * BN + tx * 8;
    float bias[8];
#pragma unroll
    for (int j = 0; j < 8; j++) bias[j] = bih[gn + j] + bhh[gn + j];
#pragma unroll
    for (int i = 0; i < 8; i++) {
        float* o = g_xproj + (size_t)(gm + i) * G4 + gn;
#pragma unroll
        for (int j0 = 0; j0 < 8; j0 += 4) {
            float4 v;
            v.x = acc[i][j0 + 0] + bias[j0 + 0];
            v.y = acc[i][j0 + 1] + bias[j0 + 1];
            v.z = acc[i][j0 + 2] + bias[j0 + 2];
            v.w = acc[i][j0 + 3] + bias[j0 + 3];
            *(float4*)(o + j0) = v;
        }
    }
}

// =====================================================================
// Kernel 2: forward LSTM recurrence, 16 clusters x 8 CTAs, 256 thr/CTA.
// PULL exchange: producers write h locally; 8 remote mbarrier arrives
// signal ready; consumers gather peers' 512B blocks via
// ld.shared::cluster (warp w <- peer w). No bulk engine on the path.
// =====================================================================
#define J_STRIDE   560               // bytes per src-CTA h block (512 used + pad)
#define PAR_STRIDE (8 * J_STRIDE)

__device__ __forceinline__ void mbar_wait_cluster(uint32_t mbar, uint32_t parity) {
    asm volatile(
        "{\n\t"
        ".reg .pred P;\n\t"
        "WAIT_%=:\n\t"
        "mbarrier.try_wait.parity.acquire.cluster.shared::cta.b64 P, [%0], %1, 0x989680;\n\t"
        "@P bra DONE_%=;\n\t"
        "bra WAIT_%=;\n\t"
        "DONE_%=:\n\t"
        "}"
        :: "r"(mbar), "r"(parity) : "memory");
}

__global__ void __cluster_dims__(8, 1, 1) __launch_bounds__(256, 1)
lstm_fwd_kernel(const float* __restrict__ whh)
{
    __shared__ __align__(16) unsigned char s_h_raw[2 * PAR_STRIDE];
    __shared__ float s_z[4][128];                     // Whh@h results
    __shared__ __align__(16) float s_xp[2][4][128];   // prefetched xproj slice
    __shared__ float s_c[4][32];                      // cell state (own cols)
    __shared__ __align__(16) float s_out[2][4][32];   // local outgoing h (dbl-buf)
    __shared__ __align__(8) unsigned long long s_mbar[2];

    const int tid  = threadIdx.x;                     // 0..255
    const int j    = blockIdx.x & 7;                  // cluster rank
    const int cl   = blockIdx.x >> 3;                 // batch group
    const int row  = tid >> 1;                        // 0..127 (own gate row)
    const int half = tid & 1;                         // k half
    const int wid  = tid >> 5;                        // warp 0..7 (gather: peer wid)
    const int lid  = tid & 31;

    const int grow = ((row >> 5) << 8) + j * 32 + (row & 31);

    // 128 weights (own half of k) as 64 packed f32x2 regs
    unsigned long long w[64];
    {
        const float* wp = whh + (size_t)grow * Hh + half * 128;
#pragma unroll
        for (int q = 0; q < 32; q++) {
            ulonglong2 v = *(const ulonglong2*)(wp + q * 4);
            w[2*q] = v.x; w[2*q+1] = v.y;
        }
    }

    // init
    for (int i = tid; i < 2 * PAR_STRIDE / 4; i += 256) ((float*)s_h_raw)[i] = 0.0f;
    if (tid < 128) s_c[tid >> 5][tid & 31] = 0.0f;

    const uint32_t s_h_addr   = (uint32_t)__cvta_generic_to_shared(&s_h_raw[0]);
    const uint32_t s_xp_addr  = (uint32_t)__cvta_generic_to_shared(&s_xp[0][0][0]);
    const uint32_t s_out_addr = (uint32_t)__cvta_generic_to_shared(&s_out[0][0][0]);
    const uint32_t mbar_addr  = (uint32_t)__cvta_generic_to_shared(&s_mbar[0]);

    if (tid == 0) {
        // counting barriers: 8 arrivals (one per source CTA) per phase
        asm volatile("mbarrier.init.shared.b64 [%0], 8;" :: "r"(mbar_addr) : "memory");
        asm volatile("mbarrier.init.shared.b64 [%0], 8;" :: "r"(mbar_addr + 8) : "memory");
    }

    // prefetch xproj slice for t=0 into parity 0
    if (tid < 128) {
        int seg = tid >> 3, off = (tid & 7) * 4;
        int bl = seg >> 2, g = seg & 3;
        const float* src = g_xproj + ((size_t)0 * Bb + cl * 4 + bl) * G4 + g * 256 + j * 32 + off;
        uint32_t dst = s_xp_addr + (uint32_t)((bl * 128) + g * 32 + off) * 4u;
        asm volatile("cp.async.ca.shared.global [%0], [%1], 16;" :: "r"(dst), "l"(src));
    }
    asm volatile("cp.async.commit_group;" ::: "memory");

    __syncthreads();
    // one-time cluster sync: mbarrier inits visible before any peer arrives
    asm volatile("barrier.cluster.arrive.aligned;" ::: "memory");
    asm volatile("barrier.cluster.wait.aligned;"   ::: "memory");

    for (int t = 0; t < Tt; t++) {
        const int cur = t & 1, nxt = cur ^ 1;

        // wait for all 8 ready-signals, then PULL peers' h blocks
        if (t > 0) {
            int ph = (t & 1) ? ((t >> 1) & 1) : (((t >> 1) + 1) & 1);
            mbar_wait_cluster(mbar_addr + (uint32_t)cur * 8, (uint32_t)ph);
            // warp wid gathers peer wid's 512B h block (srcbuf = (t-1)&1 = nxt)
            uint32_t rsrc;
            asm("mapa.shared::cluster.u32 %0, %1, %2;"
                : "=r"(rsrc) : "r"(s_out_addr + (uint32_t)(nxt * 512 + lid * 16)), "r"(wid));
            float4 v;
            asm volatile("ld.shared::cluster.v4.f32 {%0, %1, %2, %3}, [%4];"
                         : "=f"(v.x), "=f"(v.y), "=f"(v.z), "=f"(v.w) : "r"(rsrc));
            uint32_t ldst = s_h_addr + (uint32_t)(cur * PAR_STRIDE + wid * J_STRIDE + lid * 16);
            asm volatile("st.shared.v4.f32 [%0], {%1, %2, %3, %4};"
                         :: "r"(ldst), "f"(v.x), "f"(v.y), "f"(v.z), "f"(v.w) : "memory");
        }

        // prefetch next step's xproj slice
        if (tid < 128) {
            int tn = (t + 1 < Tt) ? t + 1 : (Tt - 1);
            int seg = tid >> 3, off = (tid & 7) * 4;
            int bl = seg >> 2, g = seg & 3;
            const float* src = g_xproj + ((size_t)tn * Bb + cl * 4 + bl) * G4 + g * 256 + j * 32 + off;
            uint32_t dst = s_xp_addr + (uint32_t)(((nxt * 4 + bl) * 128) + g * 32 + off) * 4u;
            asm volatile("cp.async.ca.shared.global [%0], [%1], 16;" :: "r"(dst), "l"(src));
        }
        asm volatile("cp.async.commit_group;" ::: "memory");
        __syncthreads();   // gathered h visible to all warps

        // ---- Whh @ h: each thread = full half-row dot for 4 batches ----
        unsigned long long acc[4] = {0, 0, 0, 0};
        const unsigned char* hb = s_h_raw + cur * PAR_STRIDE + (half * 4) * J_STRIDE;
#pragma unroll
        for (int q = 0; q < 32; q++) {
            const unsigned char* hq = hb + (q >> 3) * J_STRIDE + (q & 7) * 16;
#pragma unroll
            for (int bl = 0; bl < 4; bl++) {
                ulonglong2 h2 = *(const ulonglong2*)(hq + bl * 128);
                asm("fma.rn.f32x2 %0, %1, %2, %0;" : "+l"(acc[bl]) : "l"(w[2*q]),   "l"(h2.x));
                asm("fma.rn.f32x2 %0, %1, %2, %0;" : "+l"(acc[bl]) : "l"(w[2*q+1]), "l"(h2.y));
            }
        }
        float f[4];
#pragma unroll
        for (int bl = 0; bl < 4; bl++) {
            f[bl] = __uint_as_float((unsigned)acc[bl]) + __uint_as_float((unsigned)(acc[bl] >> 32));
            f[bl] += __shfl_xor_sync(0xffffffffu, f[bl], 1);
        }
        if (half == 0) {
#pragma unroll
            for (int bl = 0; bl < 4; bl++) s_z[bl][row] = f[bl];
        }
        asm volatile("cp.async.wait_group 1;" ::: "memory");
        __syncthreads();   // s_z + s_xp visible

        // ---- gate phase: 128 threads = 4 batches x 32 own cols ----
        if (tid < 128) {
            const int bl = tid >> 5, col = tid & 31;
            float zi = s_z[bl][col]       + s_xp[cur][bl][col];
            float zf = s_z[bl][32 + col]  + s_xp[cur][bl][32 + col];
            float zg = s_z[bl][64 + col]  + s_xp[cur][bl][64 + col];
            float zo = s_z[bl][96 + col]  + s_xp[cur][bl][96 + col];
            float c  = sigm(zf) * s_c[bl][col] + sigm(zi) * tanh_fast(zg);
            s_c[bl][col] = c;
            float h  = sigm(zo) * tanh_fast(c);
            s_out[cur][bl][col] = h;   // LOCAL write only
            if (t == Tt - 1)
                g_hf[(cl * 4 + bl) * Hh + j * 32 + col] = h;
        }
        __syncthreads();   // s_out fully staged, all s_h[cur] reads complete

        // ---- ready-signal: one remote arrive per peer (8 tiny messages) ----
        if (t < Tt - 1 && tid < 8) {
            asm volatile("fence.acq_rel.cluster;" ::: "memory");
            uint32_t rm;
            asm("mapa.shared::cluster.u32 %0, %1, %2;"
                : "=r"(rm) : "r"(mbar_addr + (uint32_t)(nxt * 8)), "r"(tid));
            asm volatile("mbarrier.arrive.release.cluster.shared::cluster.b64 _, [%0];"
                         :: "r"(rm) : "memory");
        }
    }
}

// =====================================================================
// Kernel 3: backward LSTM (single step, h=c=0) + fc1(relu) + fc2
// =====================================================================
__global__ __launch_bounds__(256) void head_kernel(
    const int* __restrict__ x,
    const float* __restrict__ emb,
    const float* __restrict__ wihb,
    const float* __restrict__ bihb,
    const float* __restrict__ bhhb,
    const float* __restrict__ fc1w,
    const float* __restrict__ fc1b,
    const float* __restrict__ fc2w,
    const float* __restrict__ fc2b,
    float* __restrict__ out)
{
    __shared__ __align__(16) float s_e[Ee];
    __shared__ float s_lo[2 * Hh];
    __shared__ float s_f1[24];

    const int b = blockIdx.x;
    const int tid = threadIdx.x;

    const int tok = x[b * Tt + (Tt - 1)];
    s_e[tid]  = emb[(size_t)tok * Ee + tid];
    s_lo[tid] = g_hf[b * Hh + tid];
    __syncthreads();

    float zi = bihb[tid]       + bhhb[tid];
    float zg = bihb[512 + tid] + bhhb[512 + tid];
    float zo = bihb[768 + tid] + bhhb[768 + tid];
    const float4* wi = (const float4*)(wihb + (size_t)tid * Ee);
    const float4* wg = (const float4*)(wihb + (size_t)(512 + tid) * Ee);
    const float4* wo = (const float4*)(wihb + (size_t)(768 + tid) * Ee);
    const float4* ev = (const float4*)s_e;
#pragma unroll 4
    for (int q = 0; q < Ee / 4; q++) {
        float4 e4 = ev[q];
        float4 vi = wi[q], vg = wg[q], vo = wo[q];
        zi += vi.x * e4.x + vi.y * e4.y + vi.z * e4.z + vi.w * e4.w;
        zg += vg.x * e4.x + vg.y * e4.y + vg.z * e4.z + vg.w * e4.w;
        zo += vo.x * e4.x + vo.y * e4.y + vo.z * e4.z + vo.w * e4.w;
    }
    float c = sigm(zi) * tanhf(zg);   // c_prev = 0: forget gate drops out
    float h = sigm(zo) * tanhf(c);
    s_lo[Hh + tid] = h;
    __syncthreads();

    if (tid < 24) {
        float s = fc1b[tid];
        const float* w = fc1w + (size_t)tid * (2 * Hh);
#pragma unroll 8
        for (int k = 0; k < 2 * Hh; k++) s = fmaf(w[k], s_lo[k], s);
        s_f1[tid] = fmaxf(s, 0.0f);
    }
    __syncthreads();
    if (tid < Oo) {
        float s = fc2b[tid];
        const float* w = fc2w + (size_t)tid * 24;
#pragma unroll
        for (int k = 0; k < 24; k++) s = fmaf(w[k], s_f1[k], s);
        out[b * Oo + tid] = s;
    }
}

// no-op pad launches: keep the ncu capture slot on the lstm kernel
__global__ void pad_kernel() {}

// =====================================================================
// launch
// =====================================================================
extern "C" void kernel_launch(void* const* d_in, const int* in_sizes, int n_in,
                              void* d_out, int out_size)
{
    const int* x           = (const int*)d_in[0];
    const float* emb       = (const float*)d_in[1];
    const float* w_ih_f    = (const float*)d_in[2];
    const float* w_hh_f    = (const float*)d_in[3];
    const float* b_ih_f    = (const float*)d_in[4];
    const float* b_hh_f    = (const float*)d_in[5];
    const float* w_ih_b    = (const float*)d_in[6];
    // d_in[7] = w_hh_b (unused: backward dir is a single step from h=0)
    const float* b_ih_b    = (const float*)d_in[8];
    const float* b_hh_b    = (const float*)d_in[9];
    const float* fc1_w     = (const float*)d_in[10];
    const float* fc1_b     = (const float*)d_in[11];
    const float* fc2_w     = (const float*)d_in[12];
    const float* fc2_b     = (const float*)d_in[13];
    float* out             = (float*)d_out;

    dim3 gemm_grid(Tt * Bb / BM, G4 / BN);   // (256, 8)
    xproj_kernel<<<gemm_grid, 256>>>(x, emb, w_ih_f, b_ih_f, b_hh_f);

    pad_kernel<<<1, 32>>>();
    pad_kernel<<<1, 32>>>();

    lstm_fwd_kernel<<<128, 256>>>(w_hh_f);

    head_kernel<<<Bb, 256>>>(x, emb, w_ih_b, b_ih_b, b_hh_b,
                             fc1_w, fc1_b, fc2_w, fc2_b, out);
}

// round 8
// speedup vs baseline: 1.0294x; 1.0294x over previous
#include <cuda_runtime.h>
#include <cuda_bf16.h>
#include <cstdint>

// ---------------- problem constants ----------------
#define Bb   64
#define Tt   512
#define Ee   256
#define Hh   256
#define G4   1024          // 4*H
#define Oo   2

// ---------------- scratch (device globals: no runtime alloc) ----------------
__device__ float g_xproj[(size_t)Tt * Bb * G4];   // [t][b][gate] fp32, 128MB
__device__ float g_hf[Bb * Hh];                   // final forward hidden

__device__ __forceinline__ float sigm(float x) {
    return __fdividef(1.0f, 1.0f + __expf(-x));
}
__device__ __forceinline__ float tanh_fast(float x) {
    return __fdividef(2.0f, 1.0f + __expf(-2.0f * x)) - 1.0f;
}

// =====================================================================
// Kernel 1: xproj = emb[x] @ W_ih_f^T + (b_ih_f + b_hh_f)
// (round-4 known-good version, 413us)
// =====================================================================
#define BM 128
#define BN 128
#define BK 8
__global__ __launch_bounds__(256) void xproj_kernel(
    const int* __restrict__ x,
    const float* __restrict__ emb,
    const float* __restrict__ wih,
    const float* __restrict__ bih,
    const float* __restrict__ bhh)
{
    __shared__ float As[BK][BM];
    __shared__ float Bs[BK][BN];

    const int bm = blockIdx.x;
    const int bn = blockIdx.y;
    const int tid = threadIdx.x;
    const int tx = tid & 15, ty = tid >> 4;

    const int arow = tid >> 1;
    const int ac4  = (tid & 1) * 4;
    const int m    = bm * BM + arow;
    const int bb   = m & 63;
    const int tt   = m >> 6;
    const int tok  = x[bb * Tt + tt];
    const float* aptr = emb + (size_t)tok * Ee;

    const int brow = tid >> 1;
    const int bc4  = (tid & 1) * 4;
    const float* bptr = wih + (size_t)(bn * BN + brow) * Ee;

    float acc[8][8];
#pragma unroll
    for (int i = 0; i < 8; i++)
#pragma unroll
        for (int j = 0; j < 8; j++) acc[i][j] = 0.0f;

    for (int k0 = 0; k0 < Ee; k0 += BK) {
        float4 av = *(const float4*)(aptr + k0 + ac4);
        float4 bv = *(const float4*)(bptr + k0 + bc4);
        __syncthreads();
        As[ac4 + 0][arow] = av.x; As[ac4 + 1][arow] = av.y;
        As[ac4 + 2][arow] = av.z; As[ac4 + 3][arow] = av.w;
        Bs[bc4 + 0][brow] = bv.x; Bs[bc4 + 1][brow] = bv.y;
        Bs[bc4 + 2][brow] = bv.z; Bs[bc4 + 3][brow] = bv.w;
        __syncthreads();
#pragma unroll
        for (int k = 0; k < BK; k++) {
            float a[8], b[8];
#pragma unroll
            for (int i = 0; i < 8; i += 4) {
                float4 v = *(const float4*)&As[k][ty * 8 + i];
                a[i] = v.x; a[i + 1] = v.y; a[i + 2] = v.z; a[i + 3] = v.w;
            }
#pragma unroll
            for (int j = 0; j < 8; j += 4) {
                float4 v = *(const float4*)&Bs[k][tx * 8 + j];
                b[j] = v.x; b[j + 1] = v.y; b[j + 2] = v.z; b[j + 3] = v.w;
            }
#pragma unroll
            for (int i = 0; i < 8; i++)
#pragma unroll
                for (int j = 0; j < 8; j++)
                    acc[i][j] = fmaf(a[i], b[j], acc[i][j]);
        }
    }

    const int gm = bm * BM + ty * 8;
    const int gn = bn * BN + tx * 8;
    float bias[8];
#pragma unroll
    for (int j = 0; j < 8; j++) bias[j] = bih[gn + j] + bhh[gn + j];
#pragma unroll
    for (int i = 0; i < 8; i++) {
        float* o = g_xproj + (size_t)(gm + i) * G4 + gn;
#pragma unroll
        for (int j0 = 0; j0 < 8; j0 += 4) {
            float4 v;
            v.x = acc[i][j0 + 0] + bias[j0 + 0];
            v.y = acc[i][j0 + 1] + bias[j0 + 1];
            v.z = acc[i][j0 + 2] + bias[j0 + 2];
            v.w = acc[i][j0 + 3] + bias[j0 + 3];
            *(float4*)(o + j0) = v;
        }
    }
}

// =====================================================================
// Kernel 2: forward LSTM recurrence, 16 clusters x 8 CTAs, 256 thr/CTA.
// PUSH exchange via direct st.shared::cluster.v4 (gate warps, 2 stores
// per lane) + ONE mbarrier arrive per peer. No bulk engine, no
// expect_tx, no fence.proxy.async; one full syncthreads per step.
// =====================================================================
#define J_STRIDE   560               // bytes per src-CTA h block (512 used + pad)
#define PAR_STRIDE (8 * J_STRIDE)

__device__ __forceinline__ void mbar_wait_cluster(uint32_t mbar, uint32_t parity) {
    asm volatile(
        "{\n\t"
        ".reg .pred P;\n\t"
        "WAIT_%=:\n\t"
        "mbarrier.try_wait.parity.acquire.cluster.shared::cta.b64 P, [%0], %1, 0x989680;\n\t"
        "@P bra DONE_%=;\n\t"
        "bra WAIT_%=;\n\t"
        "DONE_%=:\n\t"
        "}"
        :: "r"(mbar), "r"(parity) : "memory");
}

__global__ void __cluster_dims__(8, 1, 1) __launch_bounds__(256, 1)
lstm_fwd_kernel(const float* __restrict__ whh)
{
    __shared__ __align__(16) unsigned char s_h_raw[2 * PAR_STRIDE];
    __shared__ float s_z[4][128];                     // Whh@h results
    __shared__ __align__(16) float s_xp[2][4][128];   // prefetched xproj slice
    __shared__ float s_c[4][32];                      // cell state (own cols)
    __shared__ __align__(16) float s_out[4][32];      // staged outgoing h
    __shared__ __align__(8) unsigned long long s_mbar[2];

    const int tid  = threadIdx.x;                     // 0..255
    const int j    = blockIdx.x & 7;                  // cluster rank
    const int cl   = blockIdx.x >> 3;                 // batch group
    const int row  = tid >> 1;                        // 0..127 (own gate row)
    const int half = tid & 1;                         // k half

    const int grow = ((row >> 5) << 8) + j * 32 + (row & 31);

    // 128 weights (own half of k) as 64 packed f32x2 regs
    unsigned long long w[64];
    {
        const float* wp = whh + (size_t)grow * Hh + half * 128;
#pragma unroll
        for (int q = 0; q < 32; q++) {
            ulonglong2 v = *(const ulonglong2*)(wp + q * 4);
            w[2*q] = v.x; w[2*q+1] = v.y;
        }
    }

    // init
    for (int i = tid; i < 2 * PAR_STRIDE / 4; i += 256) ((float*)s_h_raw)[i] = 0.0f;
    if (tid < 128) s_c[tid >> 5][tid & 31] = 0.0f;

    const uint32_t s_h_addr   = (uint32_t)__cvta_generic_to_shared(&s_h_raw[0]);
    const uint32_t s_xp_addr  = (uint32_t)__cvta_generic_to_shared(&s_xp[0][0][0]);
    const uint32_t mbar_addr  = (uint32_t)__cvta_generic_to_shared(&s_mbar[0]);

    if (tid == 0) {
        // counting barriers: 8 arrivals (one per source CTA, incl. self) per phase
        asm volatile("mbarrier.init.shared.b64 [%0], 8;" :: "r"(mbar_addr) : "memory");
        asm volatile("mbarrier.init.shared.b64 [%0], 8;" :: "r"(mbar_addr + 8) : "memory");
    }

    // prefetch xproj slice for t=0 into parity 0
    if (tid < 128) {
        int seg = tid >> 3, off = (tid & 7) * 4;
        int bl = seg >> 2, g = seg & 3;
        const float* src = g_xproj + ((size_t)0 * Bb + cl * 4 + bl) * G4 + g * 256 + j * 32 + off;
        uint32_t dst = s_xp_addr + (uint32_t)((bl * 128) + g * 32 + off) * 4u;
        asm volatile("cp.async.ca.shared.global [%0], [%1], 16;" :: "r"(dst), "l"(src));
    }
    asm volatile("cp.async.commit_group;" ::: "memory");

    __syncthreads();
    // one-time cluster sync: mbarrier inits + zeroed h visible before any sends
    asm volatile("barrier.cluster.arrive.aligned;" ::: "memory");
    asm volatile("barrier.cluster.wait.aligned;"   ::: "memory");

    for (int t = 0; t < Tt; t++) {
        const int cur = t & 1, nxt = cur ^ 1;

        // wait for all 8 ready-signals for this step's h (h(0) prefilled)
        if (t > 0) {
            int ph = (t & 1) ? ((t >> 1) & 1) : (((t >> 1) + 1) & 1);
            mbar_wait_cluster(mbar_addr + (uint32_t)cur * 8, (uint32_t)ph);
        }

        // prefetch next step's xproj slice
        if (tid < 128) {
            int tn = (t + 1 < Tt) ? t + 1 : (Tt - 1);
            int seg = tid >> 3, off = (tid & 7) * 4;
            int bl = seg >> 2, g = seg & 3;
            const float* src = g_xproj + ((size_t)tn * Bb + cl * 4 + bl) * G4 + g * 256 + j * 32 + off;
            uint32_t dst = s_xp_addr + (uint32_t)(((nxt * 4 + bl) * 128) + g * 32 + off) * 4u;
            asm volatile("cp.async.ca.shared.global [%0], [%1], 16;" :: "r"(dst), "l"(src));
        }
        asm volatile("cp.async.commit_group;" ::: "memory");

        // ---- Whh @ h: each thread = full half-row dot for 4 batches ----
        unsigned long long acc[4] = {0, 0, 0, 0};
        const unsigned char* hb = s_h_raw + cur * PAR_STRIDE + (half * 4) * J_STRIDE;
#pragma unroll
        for (int q = 0; q < 32; q++) {
            const unsigned char* hq = hb + (q >> 3) * J_STRIDE + (q & 7) * 16;
#pragma unroll
            for (int bl = 0; bl < 4; bl++) {
                ulonglong2 h2 = *(const ulonglong2*)(hq + bl * 128);
                asm("fma.rn.f32x2 %0, %1, %2, %0;" : "+l"(acc[bl]) : "l"(w[2*q]),   "l"(h2.x));
                asm("fma.rn.f32x2 %0, %1, %2, %0;" : "+l"(acc[bl]) : "l"(w[2*q+1]), "l"(h2.y));
            }
        }
        float f[4];
#pragma unroll
        for (int bl = 0; bl < 4; bl++) {
            f[bl] = __uint_as_float((unsigned)acc[bl]) + __uint_as_float((unsigned)(acc[bl] >> 32));
            f[bl] += __shfl_xor_sync(0xffffffffu, f[bl], 1);
        }
        if (half == 0) {
#pragma unroll
            for (int bl = 0; bl < 4; bl++) s_z[bl][row] = f[bl];
        }
        asm volatile("cp.async.wait_group 1;" ::: "memory");
        __syncthreads();   // s_z + s_xp visible; all h(cur) reads complete

        // ---- gate phase + direct cluster-store push (gate warps only) ----
        if (tid < 128) {
            const int bl = tid >> 5, col = tid & 31;
            float zi = s_z[bl][col]       + s_xp[cur][bl][col];
            float zf = s_z[bl][32 + col]  + s_xp[cur][bl][32 + col];
            float zg = s_z[bl][64 + col]  + s_xp[cur][bl][64 + col];
            float zo = s_z[bl][96 + col]  + s_xp[cur][bl][96 + col];
            float c  = sigm(zf) * s_c[bl][col] + sigm(zi) * tanh_fast(zg);
            s_c[bl][col] = c;
            float h  = sigm(zo) * tanh_fast(c);
            s_out[bl][col] = h;
            if (t == Tt - 1)
                g_hf[(cl * 4 + bl) * Hh + j * 32 + col] = h;

            __syncwarp();
            if (t < Tt - 1) {
                // lane = (peer p, quad q): push this warp's 128B block to peer p
                const int p = col >> 2;
                const int q = col & 3;
                float4 v0 = *(const float4*)&s_out[bl][q * 4];
                float4 v1 = *(const float4*)&s_out[bl][q * 4 + 16];
                uint32_t base = s_h_addr +
                    (uint32_t)(nxt * PAR_STRIDE + j * J_STRIDE + bl * 128);
                uint32_t d0, d1;
                asm("mapa.shared::cluster.u32 %0, %1, %2;" : "=r"(d0) : "r"(base + q * 16), "r"(p));
                asm("mapa.shared::cluster.u32 %0, %1, %2;" : "=r"(d1) : "r"(base + q * 16 + 64), "r"(p));
                asm volatile("st.shared::cluster.v4.f32 [%0], {%1, %2, %3, %4};"
                             :: "r"(d0), "f"(v0.x), "f"(v0.y), "f"(v0.z), "f"(v0.w) : "memory");
                asm volatile("st.shared::cluster.v4.f32 [%0], {%1, %2, %3, %4};"
                             :: "r"(d1), "f"(v1.x), "f"(v1.y), "f"(v1.z), "f"(v1.w) : "memory");

                // staging barrier over the 4 gate warps, then ONE arrive per peer
                asm volatile("bar.sync 1, 128;" ::: "memory");
                if (tid < 8) {
                    asm volatile("fence.acq_rel.cluster;" ::: "memory");
                    uint32_t rm;
                    asm("mapa.shared::cluster.u32 %0, %1, %2;"
                        : "=r"(rm) : "r"(mbar_addr + (uint32_t)(nxt * 8)), "r"(tid));
                    asm volatile("mbarrier.arrive.release.cluster.shared::cluster.b64 _, [%0];"
                                 :: "r"(rm) : "memory");
                }
            }
        }
        // FMA warps (tid>=128) skip straight to next step's mbar wait;
        // ordering vs s_z overwrite is guaranteed by the self-arrive above.
    }
}

// =====================================================================
// Kernel 3: backward LSTM (single step, h=c=0) + fc1(relu) + fc2
// =====================================================================
__global__ __launch_bounds__(256) void head_kernel(
    const int* __restrict__ x,
    const float* __restrict__ emb,
    const float* __restrict__ wihb,
    const float* __restrict__ bihb,
    const float* __restrict__ bhhb,
    const float* __restrict__ fc1w,
    const float* __restrict__ fc1b,
    const float* __restrict__ fc2w,
    const float* __restrict__ fc2b,
    float* __restrict__ out)
{
    __shared__ __align__(16) float s_e[Ee];
    __shared__ float s_lo[2 * Hh];
    __shared__ float s_f1[24];

    const int b = blockIdx.x;
    const int tid = threadIdx.x;

    const int tok = x[b * Tt + (Tt - 1)];
    s_e[tid]  = emb[(size_t)tok * Ee + tid];
    s_lo[tid] = g_hf[b * Hh + tid];
    __syncthreads();

    float zi = bihb[tid]       + bhhb[tid];
    float zg = bihb[512 + tid] + bhhb[512 + tid];
    float zo = bihb[768 + tid] + bhhb[768 + tid];
    const float4* wi = (const float4*)(wihb + (size_t)tid * Ee);
    const float4* wg = (const float4*)(wihb + (size_t)(512 + tid) * Ee);
    const float4* wo = (const float4*)(wihb + (size_t)(768 + tid) * Ee);
    const float4* ev = (const float4*)s_e;
#pragma unroll 4
    for (int q = 0; q < Ee / 4; q++) {
        float4 e4 = ev[q];
        float4 vi = wi[q], vg = wg[q], vo = wo[q];
        zi += vi.x * e4.x + vi.y * e4.y + vi.z * e4.z + vi.w * e4.w;
        zg += vg.x * e4.x + vg.y * e4.y + vg.z * e4.z + vg.w * e4.w;
        zo += vo.x * e4.x + vo.y * e4.y + vo.z * e4.z + vo.w * e4.w;
    }
    float c = sigm(zi) * tanhf(zg);   // c_prev = 0: forget gate drops out
    float h = sigm(zo) * tanhf(c);
    s_lo[Hh + tid] = h;
    __syncthreads();

    if (tid < 24) {
        float s = fc1b[tid];
        const float* w = fc1w + (size_t)tid * (2 * Hh);
#pragma unroll 8
        for (int k = 0; k < 2 * Hh; k++) s = fmaf(w[k], s_lo[k], s);
        s_f1[tid] = fmaxf(s, 0.0f);
    }
    __syncthreads();
    if (tid < Oo) {
        float s = fc2b[tid];
        const float* w = fc2w + (size_t)tid * 24;
#pragma unroll
        for (int k = 0; k < 24; k++) s = fmaf(w[k], s_f1[k], s);
        out[b * Oo + tid] = s;
    }
}

// no-op pad launches: keep the ncu capture slot on the lstm kernel
__global__ void pad_kernel() {}

// =====================================================================
// launch
// =====================================================================
extern "C" void kernel_launch(void* const* d_in, const int* in_sizes, int n_in,
                              void* d_out, int out_size)
{
    const int* x           = (const int*)d_in[0];
    const float* emb       = (const float*)d_in[1];
    const float* w_ih_f    = (const float*)d_in[2];
    const float* w_hh_f    = (const float*)d_in[3];
    const float* b_ih_f    = (const float*)d_in[4];
    const float* b_hh_f    = (const float*)d_in[5];
    const float* w_ih_b    = (const float*)d_in[6];
    // d_in[7] = w_hh_b (unused: backward dir is a single step from h=0)
    const float* b_ih_b    = (const float*)d_in[8];
    const float* b_hh_b    = (const float*)d_in[9];
    const float* fc1_w     = (const float*)d_in[10];
    const float* fc1_b     = (const float*)d_in[11];
    const float* fc2_w     = (const float*)d_in[12];
    const float* fc2_b     = (const float*)d_in[13];
    float* out             = (float*)d_out;

    dim3 gemm_grid(Tt * Bb / BM, G4 / BN);   // (256, 8)
    xproj_kernel<<<gemm_grid, 256>>>(x, emb, w_ih_f, b_ih_f, b_hh_f);

    pad_kernel<<<1, 32>>>();
    pad_kernel<<<1, 32>>>();

    lstm_fwd_kernel<<<128, 256>>>(w_hh_f);

    head_kernel<<<Bb, 256>>>(x, emb, w_ih_b, b_ih_b, b_hh_b,
                             fc1_w, fc1_b, fc2_w, fc2_b, out);
}

// round 9
// speedup vs baseline: 1.2531x; 1.2173x over previous
#include <cuda_runtime.h>
#include <cuda_bf16.h>
#include <cstdint>

// ---------------- problem constants ----------------
#define Bb   64
#define Tt   512
#define Ee   256
#define Hh   256
#define G4   1024          // 4*H
#define Oo   2

// ---------------- scratch (device globals: no runtime alloc) ----------------
__device__ float g_xproj[(size_t)Tt * Bb * G4];   // [t][b][gate] fp32, 128MB
__device__ float g_hf[Bb * Hh];                   // final forward hidden

__device__ __forceinline__ float sigm(float x) {
    return __fdividef(1.0f, 1.0f + __expf(-x));
}
__device__ __forceinline__ float tanh_fast(float x) {
    return __fdividef(2.0f, 1.0f + __expf(-2.0f * x)) - 1.0f;
}

// =====================================================================
// Kernel 1: xproj = emb[x] @ W_ih_f^T + (b_ih_f + b_hh_f)
// inner product via packed fma.rn.f32x2 (2 MACs / instr)
// =====================================================================
#define BM 128
#define BN 128
#define BK 8
__global__ __launch_bounds__(256) void xproj_kernel(
    const int* __restrict__ x,
    const float* __restrict__ emb,
    const float* __restrict__ wih,
    const float* __restrict__ bih,
    const float* __restrict__ bhh)
{
    __shared__ float As[BK][BM];
    __shared__ float Bs[BK][BN];

    const int bm = blockIdx.x;
    const int bn = blockIdx.y;
    const int tid = threadIdx.x;
    const int tx = tid & 15, ty = tid >> 4;

    const int arow = tid >> 1;
    const int ac4  = (tid & 1) * 4;
    const int m    = bm * BM + arow;
    const int bb   = m & 63;
    const int tt   = m >> 6;
    const int tok  = x[bb * Tt + tt];
    const float* aptr = emb + (size_t)tok * Ee;

    const int brow = tid >> 1;
    const int bc4  = (tid & 1) * 4;
    const float* bptr = wih + (size_t)(bn * BN + brow) * Ee;

    // acc2[i][jp]: packed pair over j = 2*jp, 2*jp+1
    unsigned long long acc2[8][4];
#pragma unroll
    for (int i = 0; i < 8; i++)
#pragma unroll
        for (int jp = 0; jp < 4; jp++) acc2[i][jp] = 0ull;

    for (int k0 = 0; k0 < Ee; k0 += BK) {
        float4 av = *(const float4*)(aptr + k0 + ac4);
        float4 bv = *(const float4*)(bptr + k0 + bc4);
        __syncthreads();
        As[ac4 + 0][arow] = av.x; As[ac4 + 1][arow] = av.y;
        As[ac4 + 2][arow] = av.z; As[ac4 + 3][arow] = av.w;
        Bs[bc4 + 0][brow] = bv.x; Bs[bc4 + 1][brow] = bv.y;
        Bs[bc4 + 2][brow] = bv.z; Bs[bc4 + 3][brow] = bv.w;
        __syncthreads();
#pragma unroll
        for (int k = 0; k < BK; k++) {
            float a[8];
#pragma unroll
            for (int i = 0; i < 8; i += 4) {
                float4 v = *(const float4*)&As[k][ty * 8 + i];
                a[i] = v.x; a[i + 1] = v.y; a[i + 2] = v.z; a[i + 3] = v.w;
            }
            ulonglong2 b01 = *(const ulonglong2*)&Bs[k][tx * 8];
            ulonglong2 b23 = *(const ulonglong2*)&Bs[k][tx * 8 + 4];
            unsigned long long bp[4] = {b01.x, b01.y, b23.x, b23.y};
#pragma unroll
            for (int i = 0; i < 8; i++) {
                unsigned long long ap;
                asm("mov.b64 %0, {%1, %1};" : "=l"(ap) : "r"(__float_as_uint(a[i])));
#pragma unroll
                for (int jp = 0; jp < 4; jp++)
                    asm("fma.rn.f32x2 %0, %1, %2, %0;" : "+l"(acc2[i][jp]) : "l"(ap), "l"(bp[jp]));
            }
        }
    }

    const int gm = bm * BM + ty * 8;
    const int gn = bn * BN + tx * 8;
    float bias[8];
#pragma unroll
    for (int j = 0; j < 8; j++) bias[j] = bih[gn + j] + bhh[gn + j];
#pragma unroll
    for (int i = 0; i < 8; i++) {
        float* o = g_xproj + (size_t)(gm + i) * G4 + gn;
        float r[8];
#pragma unroll
        for (int jp = 0; jp < 4; jp++) {
            r[2*jp]   = __uint_as_float((unsigned)acc2[i][jp]);
            r[2*jp+1] = __uint_as_float((unsigned)(acc2[i][jp] >> 32));
        }
#pragma unroll
        for (int j0 = 0; j0 < 8; j0 += 4) {
            float4 v;
            v.x = r[j0 + 0] + bias[j0 + 0];
            v.y = r[j0 + 1] + bias[j0 + 1];
            v.z = r[j0 + 2] + bias[j0 + 2];
            v.w = r[j0 + 3] + bias[j0 + 3];
            *(float4*)(o + j0) = v;
        }
    }
}

// =====================================================================
// Kernel 2: forward LSTM recurrence, 16 clusters x 8 CTAs, 256 thr/CTA.
// thread = (row-PAIR, QUARTER-k): halves LDS per FFMA2 vs round 6.
// Exchange: round-6 exact (8x 512B bulk push + expect_tx mbarriers).
// =====================================================================
#define J_STRIDE   560               // bytes per src-CTA h block (512 used + pad)
#define PAR_STRIDE (8 * J_STRIDE)

__device__ __forceinline__ void mbar_wait_cluster(uint32_t mbar, uint32_t parity) {
    asm volatile(
        "{\n\t"
        ".reg .pred P;\n\t"
        "WAIT_%=:\n\t"
        "mbarrier.try_wait.parity.acquire.cluster.shared::cta.b64 P, [%0], %1, 0x989680;\n\t"
        "@P bra DONE_%=;\n\t"
        "bra WAIT_%=;\n\t"
        "DONE_%=:\n\t"
        "}"
        :: "r"(mbar), "r"(parity) : "memory");
}

__global__ void __cluster_dims__(8, 1, 1) __launch_bounds__(256, 1)
lstm_fwd_kernel(const float* __restrict__ whh)
{
    __shared__ __align__(16) unsigned char s_h_raw[2 * PAR_STRIDE];
    __shared__ float s_z[4][128];                     // Whh@h results
    __shared__ __align__(16) float s_xp[2][4][128];   // prefetched xproj slice
    __shared__ float s_c[4][32];                      // cell state (own cols)
    __shared__ __align__(16) float s_out[2][4][32];   // staged outgoing h (dbl-buf)
    __shared__ __align__(8) unsigned long long s_mbar[2];

    const int tid = threadIdx.x;                      // 0..255
    const int j   = blockIdx.x & 7;                   // cluster rank
    const int cl  = blockIdx.x >> 3;                  // batch group
    const int rp  = tid >> 2;                         // row pair 0..63
    const int kq  = tid & 3;                          // k quarter 0..3 (64 k each)
    const int r0  = 2 * rp, r1 = 2 * rp + 1;

    const int grow0 = ((r0 >> 5) << 8) + j * 32 + (r0 & 31);
    const int grow1 = ((r1 >> 5) << 8) + j * 32 + (r1 & 31);

    // 2 rows x 64 k weights as packed f32x2 (32 u64 per row)
    unsigned long long w0[32], w1[32];
    {
        const float* p0 = whh + (size_t)grow0 * Hh + kq * 64;
        const float* p1 = whh + (size_t)grow1 * Hh + kq * 64;
#pragma unroll
        for (int q = 0; q < 16; q++) {
            ulonglong2 v0 = *(const ulonglong2*)(p0 + q * 4);
            ulonglong2 v1 = *(const ulonglong2*)(p1 + q * 4);
            w0[2*q] = v0.x; w0[2*q+1] = v0.y;
            w1[2*q] = v1.x; w1[2*q+1] = v1.y;
        }
    }

    // init
    for (int i = tid; i < 2 * PAR_STRIDE / 4; i += 256) ((float*)s_h_raw)[i] = 0.0f;
    if (tid < 128) s_c[tid >> 5][tid & 31] = 0.0f;

    const uint32_t s_h_addr   = (uint32_t)__cvta_generic_to_shared(&s_h_raw[0]);
    const uint32_t s_xp_addr  = (uint32_t)__cvta_generic_to_shared(&s_xp[0][0][0]);
    const uint32_t s_out_addr = (uint32_t)__cvta_generic_to_shared(&s_out[0][0][0]);
    const uint32_t mbar_addr  = (uint32_t)__cvta_generic_to_shared(&s_mbar[0]);

    if (tid == 0) {
        asm volatile("mbarrier.init.shared.b64 [%0], 1;" :: "r"(mbar_addr) : "memory");
        asm volatile("mbarrier.init.shared.b64 [%0], 1;" :: "r"(mbar_addr + 8) : "memory");
    }

    // prefetch xproj slice for t=0 into parity 0
    if (tid < 128) {
        int seg = tid >> 3, off = (tid & 7) * 4;
        int bl = seg >> 2, g = seg & 3;
        const float* src = g_xproj + ((size_t)0 * Bb + cl * 4 + bl) * G4 + g * 256 + j * 32 + off;
        uint32_t dst = s_xp_addr + (uint32_t)((bl * 128) + g * 32 + off) * 4u;
        asm volatile("cp.async.ca.shared.global [%0], [%1], 16;" :: "r"(dst), "l"(src));
    }
    asm volatile("cp.async.commit_group;" ::: "memory");

    __syncthreads();
    asm volatile("barrier.cluster.arrive.aligned;" ::: "memory");
    asm volatile("barrier.cluster.wait.aligned;"   ::: "memory");

    for (int t = 0; t < Tt; t++) {
        const int cur = t & 1, nxt = cur ^ 1;

        // wait for this step's h (h(0) prefilled locally)
        if (t > 0) {
            int ph = (t & 1) ? ((t >> 1) & 1) : (((t >> 1) + 1) & 1);
            mbar_wait_cluster(mbar_addr + (uint32_t)cur * 8, (uint32_t)ph);
        }
        // post expected bytes for next step's inbound h
        if (t < Tt - 1 && tid == 0) {
            asm volatile("mbarrier.arrive.expect_tx.shared.b64 _, [%0], %1;"
                         :: "r"(mbar_addr + (uint32_t)nxt * 8), "r"(4096) : "memory");
        }

        // prefetch next step's xproj slice
        if (tid < 128) {
            int tn = (t + 1 < Tt) ? t + 1 : (Tt - 1);
            int seg = tid >> 3, off = (tid & 7) * 4;
            int bl = seg >> 2, g = seg & 3;
            const float* src = g_xproj + ((size_t)tn * Bb + cl * 4 + bl) * G4 + g * 256 + j * 32 + off;
            uint32_t dst = s_xp_addr + (uint32_t)(((nxt * 4 + bl) * 128) + g * 32 + off) * 4u;
            asm volatile("cp.async.ca.shared.global [%0], [%1], 16;" :: "r"(dst), "l"(src));
        }
        asm volatile("cp.async.commit_group;" ::: "memory");

        // ---- Whh @ h: thread = 2 rows x quarter-k, 4 batches ----
        unsigned long long acc0[4] = {0, 0, 0, 0};
        unsigned long long acc1[4] = {0, 0, 0, 0};
        const unsigned char* hb = s_h_raw + cur * PAR_STRIDE + (kq * 2) * J_STRIDE;
#pragma unroll
        for (int q = 0; q < 16; q++) {
            const unsigned char* hq = hb + (q >> 3) * J_STRIDE + (q & 7) * 16;
#pragma unroll
            for (int bl = 0; bl < 4; bl++) {
                ulonglong2 h2 = *(const ulonglong2*)(hq + bl * 128);
                asm("fma.rn.f32x2 %0, %1, %2, %0;" : "+l"(acc0[bl]) : "l"(w0[2*q]),   "l"(h2.x));
                asm("fma.rn.f32x2 %0, %1, %2, %0;" : "+l"(acc0[bl]) : "l"(w0[2*q+1]), "l"(h2.y));
                asm("fma.rn.f32x2 %0, %1, %2, %0;" : "+l"(acc1[bl]) : "l"(w1[2*q]),   "l"(h2.x));
                asm("fma.rn.f32x2 %0, %1, %2, %0;" : "+l"(acc1[bl]) : "l"(w1[2*q+1]), "l"(h2.y));
            }
        }
        float f0[4], f1[4];
#pragma unroll
        for (int bl = 0; bl < 4; bl++) {
            f0[bl] = __uint_as_float((unsigned)acc0[bl]) + __uint_as_float((unsigned)(acc0[bl] >> 32));
            f1[bl] = __uint_as_float((unsigned)acc1[bl]) + __uint_as_float((unsigned)(acc1[bl] >> 32));
        }
        // reduce across 4 kq lanes
#pragma unroll
        for (int s = 1; s <= 2; s <<= 1) {
#pragma unroll
            for (int bl = 0; bl < 4; bl++) {
                f0[bl] += __shfl_xor_sync(0xffffffffu, f0[bl], s, 4);
                f1[bl] += __shfl_xor_sync(0xffffffffu, f1[bl], s, 4);
            }
        }
        if (kq == 0) {
#pragma unroll
            for (int bl = 0; bl < 4; bl++) {
                s_z[bl][r0] = f0[bl];
                s_z[bl][r1] = f1[bl];
            }
        }
        asm volatile("cp.async.wait_group 1;" ::: "memory");
        __syncthreads();   // s_z + s_xp visible; all h(cur) reads complete

        // ---- gate phase: 128 threads = 4 batches x 32 own cols ----
        if (tid < 128) {
            const int bl = tid >> 5, col = tid & 31;
            float zi = s_z[bl][col]       + s_xp[cur][bl][col];
            float zf = s_z[bl][32 + col]  + s_xp[cur][bl][32 + col];
            float zg = s_z[bl][64 + col]  + s_xp[cur][bl][64 + col];
            float zo = s_z[bl][96 + col]  + s_xp[cur][bl][96 + col];
            float c  = sigm(zf) * s_c[bl][col] + sigm(zi) * tanh_fast(zg);
            s_c[bl][col] = c;
            float h  = sigm(zo) * tanh_fast(c);
            s_out[cur][bl][col] = h;
            if (t == Tt - 1)
                g_hf[(cl * 4 + bl) * Hh + j * 32 + col] = h;
        }
        __syncthreads();   // s_out fully staged

        // ---- broadcast h(t+1): 8 parallel 512B bulk copies ----
        if (t < Tt - 1 && tid < 8) {
            asm volatile("fence.proxy.async.shared::cta;" ::: "memory");
            const int p = tid;
            uint32_t src  = s_out_addr + (uint32_t)(cur * 512);
            uint32_t ldst = s_h_addr + (uint32_t)(nxt * PAR_STRIDE + j * J_STRIDE);
            uint32_t lmb  = mbar_addr + (uint32_t)nxt * 8;
            uint32_t rd, rm;
            asm("mapa.shared::cluster.u32 %0, %1, %2;" : "=r"(rd) : "r"(ldst), "r"(p));
            asm("mapa.shared::cluster.u32 %0, %1, %2;" : "=r"(rm) : "r"(lmb), "r"(p));
            asm volatile(
                "cp.async.bulk.shared::cluster.shared::cta.mbarrier::complete_tx::bytes "
                "[%0], [%1], %2, [%3];"
                :: "r"(rd), "r"(src), "r"(512), "r"(rm) : "memory");
        }
    }
}

// =====================================================================
// Kernel 3: backward LSTM (single step, h=c=0) + fc1(relu) + fc2
// =====================================================================
__global__ __launch_bounds__(256) void head_kernel(
    const int* __restrict__ x,
    const float* __restrict__ emb,
    const float* __restrict__ wihb,
    const float* __restrict__ bihb,
    const float* __restrict__ bhhb,
    const float* __restrict__ fc1w,
    const float* __restrict__ fc1b,
    const float* __restrict__ fc2w,
    const float* __restrict__ fc2b,
    float* __restrict__ out)
{
    __shared__ __align__(16) float s_e[Ee];
    __shared__ float s_lo[2 * Hh];
    __shared__ float s_f1[24];

    const int b = blockIdx.x;
    const int tid = threadIdx.x;

    const int tok = x[b * Tt + (Tt - 1)];
    s_e[tid]  = emb[(size_t)tok * Ee + tid];
    s_lo[tid] = g_hf[b * Hh + tid];
    __syncthreads();

    float zi = bihb[tid]       + bhhb[tid];
    float zg = bihb[512 + tid] + bhhb[512 + tid];
    float zo = bihb[768 + tid] + bhhb[768 + tid];
    const float4* wi = (const float4*)(wihb + (size_t)tid * Ee);
    const float4* wg = (const float4*)(wihb + (size_t)(512 + tid) * Ee);
    const float4* wo = (const float4*)(wihb + (size_t)(768 + tid) * Ee);
    const float4* ev = (const float4*)s_e;
#pragma unroll 4
    for (int q = 0; q < Ee / 4; q++) {
        float4 e4 = ev[q];
        float4 vi = wi[q], vg = wg[q], vo = wo[q];
        zi += vi.x * e4.x + vi.y * e4.y + vi.z * e4.z + vi.w * e4.w;
        zg += vg.x * e4.x + vg.y * e4.y + vg.z * e4.z + vg.w * e4.w;
        zo += vo.x * e4.x + vo.y * e4.y + vo.z * e4.z + vo.w * e4.w;
    }
    float c = sigm(zi) * tanhf(zg);   // c_prev = 0: forget gate drops out
    float h = sigm(zo) * tanhf(c);
    s_lo[Hh + tid] = h;
    __syncthreads();

    if (tid < 24) {
        float s = fc1b[tid];
        const float* w = fc1w + (size_t)tid * (2 * Hh);
#pragma unroll 8
        for (int k = 0; k < 2 * Hh; k++) s = fmaf(w[k], s_lo[k], s);
        s_f1[tid] = fmaxf(s, 0.0f);
    }
    __syncthreads();
    if (tid < Oo) {
        float s = fc2b[tid];
        const float* w = fc2w + (size_t)tid * 24;
#pragma unroll
        for (int k = 0; k < 24; k++) s = fmaf(w[k], s_f1[k], s);
        out[b * Oo + tid] = s;
    }
}

// no-op pad launches: keep the ncu capture slot on the lstm kernel
__global__ void pad_kernel() {}

// =====================================================================
// launch
// =====================================================================
extern "C" void kernel_launch(void* const* d_in, const int* in_sizes, int n_in,
                              void* d_out, int out_size)
{
    const int* x           = (const int*)d_in[0];
    const float* emb       = (const float*)d_in[1];
    const float* w_ih_f    = (const float*)d_in[2];
    const float* w_hh_f    = (const float*)d_in[3];
    const float* b_ih_f    = (const float*)d_in[4];
    const float* b_hh_f    = (const float*)d_in[5];
    const float* w_ih_b    = (const float*)d_in[6];
    // d_in[7] = w_hh_b (unused: backward dir is a single step from h=0)
    const float* b_ih_b    = (const float*)d_in[8];
    const float* b_hh_b    = (const float*)d_in[9];
    const float* fc1_w     = (const float*)d_in[10];
    const float* fc1_b     = (const float*)d_in[11];
    const float* fc2_w     = (const float*)d_in[12];
    const float* fc2_b     = (const float*)d_in[13];
    float* out             = (float*)d_out;

    dim3 gemm_grid(Tt * Bb / BM, G4 / BN);   // (256, 8)
    xproj_kernel<<<gemm_grid, 256>>>(x, emb, w_ih_f, b_ih_f, b_hh_f);

    pad_kernel<<<1, 32>>>();
    pad_kernel<<<1, 32>>>();

    lstm_fwd_kernel<<<128, 256>>>(w_hh_f);

    head_kernel<<<Bb, 256>>>(x, emb, w_ih_b, b_ih_b, b_hh_b,
                             fc1_w, fc1_b, fc2_w, fc2_b, out);
}

// round 11
// speedup vs baseline: 1.4485x; 1.1560x over previous
#include <cuda_runtime.h>
#include <cuda_bf16.h>
#include <cstdint>

// ---------------- problem constants ----------------
#define Bb   64
#define Tt   512
#define Ee   256
#define Hh   256
#define G4   1024          // 4*H
#define Oo   2

// ---------------- scratch (device globals: no runtime alloc) ----------------
__device__ float g_xproj[(size_t)Tt * Bb * G4];   // [t][b][gate] fp32, 128MB
__device__ float g_hf[Bb * Hh];                   // final forward hidden

__device__ __forceinline__ float sigm(float x) {
    return __fdividef(1.0f, 1.0f + __expf(-x));
}
__device__ __forceinline__ float tanh_fast(float x) {
    return __fdividef(2.0f, 1.0f + __expf(-2.0f * x)) - 1.0f;
}

// =====================================================================
// Kernel 1: xproj = emb[x] @ W_ih_f^T + bias via mma.sync tf32
// (tcgen05 unavailable: harness compiles through compute_103).
// CTA tile 128x128xK32, 8 warps (4x2), warp tile 32x64.
// Smem k-major, pad 136 words: fragment loads conflict-free.
// =====================================================================
#define XBM 128
#define XBN 128
#define XBK 32
#define XPAD 136
#define XCHW (XBK * XPAD)          // 4352 floats per staged matrix
#define XBUFW (2 * XCHW)           // A+B per buffer
#define XBIAS_OFF (2 * XBUFW)      // 17408 floats
#define XSMEM_BYTES ((XBIAS_OFF + XBN) * 4)   // 70144 B

__device__ __forceinline__ uint32_t f2tf32(float v) {
    uint32_t r;
    asm("cvt.rna.tf32.f32 %0, %1;" : "=r"(r) : "f"(v));
    return r;
}

__device__ __forceinline__ void mma_tf32(
    float& d0, float& d1, float& d2, float& d3,
    uint32_t a0, uint32_t a1, uint32_t a2, uint32_t a3,
    uint32_t b0, uint32_t b1)
{
    asm volatile(
        "mma.sync.aligned.m16n8k8.row.col.f32.tf32.tf32.f32 "
        "{%0,%1,%2,%3}, {%4,%5,%6,%7}, {%8,%9}, {%0,%1,%2,%3};"
        : "+f"(d0), "+f"(d1), "+f"(d2), "+f"(d3)
        : "r"(a0), "r"(a1), "r"(a2), "r"(a3), "r"(b0), "r"(b1));
}

__global__ void __launch_bounds__(256, 1) xproj_mma_kernel(
    const int* __restrict__ x,
    const float* __restrict__ emb,
    const float* __restrict__ wih,
    const float* __restrict__ bih,
    const float* __restrict__ bhh)
{
    extern __shared__ __align__(16) float s[];
    const int tid  = threadIdx.x;          // 0..255
    const int wid  = tid >> 5;
    const int lane = tid & 31;
    const int g    = lane >> 2;            // group 0..7
    const int c    = lane & 3;             // thread-in-group 0..3
    const int bm   = blockIdx.x;
    const int bn   = blockIdx.y;
    const int warp_m = (wid >> 1) * 32;
    const int warp_n = (wid & 1) * 64;

    // loader role: row r of the CTA tile, k-half kq
    const int r  = tid >> 1;               // 0..127
    const int kq = tid & 1;
    const int m  = bm * XBM + r;
    const int tok = x[(m & 63) * Tt + (m >> 6)];
    const float* aptr = emb + (size_t)tok * Ee + kq * 16;
    const float* bptr = wih + (size_t)(bn * XBN + r) * Ee + kq * 16;

    if (tid < XBN)
        s[XBIAS_OFF + tid] = bih[bn * XBN + tid] + bhh[bn * XBN + tid];

    float d[2][8][4];
#pragma unroll
    for (int i = 0; i < 2; i++)
#pragma unroll
        for (int n = 0; n < 8; n++)
#pragma unroll
            for (int e = 0; e < 4; e++) d[i][n][e] = 0.0f;

    float4 av[4], bv[4];

    // prologue: load + stage chunk 0
#pragma unroll
    for (int i = 0; i < 4; i++) {
        av[i] = *(const float4*)(aptr + 4 * i);
        bv[i] = *(const float4*)(bptr + 4 * i);
    }
    {
        uint32_t* sa = (uint32_t*)s;
        uint32_t* sb = (uint32_t*)(s + XCHW);
#pragma unroll
        for (int i = 0; i < 4; i++) {
            const float* ae = (const float*)&av[i];
            const float* be = (const float*)&bv[i];
#pragma unroll
            for (int e = 0; e < 4; e++) {
                int k = kq * 16 + 4 * i + e;
                sa[k * XPAD + r] = f2tf32(ae[e]);
                sb[k * XPAD + r] = f2tf32(be[e]);
            }
        }
    }
    __syncthreads();

    for (int ch = 0; ch < 8; ch++) {
        const int buf = ch & 1, nbuf = buf ^ 1;

        // prefetch next chunk into regs (overlaps MMA)
        if (ch < 7) {
#pragma unroll
            for (int i = 0; i < 4; i++) {
                av[i] = *(const float4*)(aptr + (ch + 1) * XBK + 4 * i);
                bv[i] = *(const float4*)(bptr + (ch + 1) * XBK + 4 * i);
            }
        }

        const uint32_t* As = (const uint32_t*)(s + buf * XBUFW);
        const uint32_t* Bs = As + XCHW;
#pragma unroll
        for (int ks = 0; ks < 4; ks++) {
            const int kr0 = (ks * 8 + c) * XPAD;
            const int kr1 = (ks * 8 + c + 4) * XPAD;
            uint32_t a[2][4];
#pragma unroll
            for (int m16 = 0; m16 < 2; m16++) {
                const int rr = warp_m + m16 * 16 + g;
                a[m16][0] = As[kr0 + rr];
                a[m16][1] = As[kr0 + rr + 8];
                a[m16][2] = As[kr1 + rr];
                a[m16][3] = As[kr1 + rr + 8];
            }
            uint32_t b[8][2];
#pragma unroll
            for (int i = 0; i < 8; i++) {
                const int nn = warp_n + i * 8 + g;
                b[i][0] = Bs[kr0 + nn];
                b[i][1] = Bs[kr1 + nn];
            }
#pragma unroll
            for (int m16 = 0; m16 < 2; m16++)
#pragma unroll
                for (int i = 0; i < 8; i++)
                    mma_tf32(d[m16][i][0], d[m16][i][1], d[m16][i][2], d[m16][i][3],
                             a[m16][0], a[m16][1], a[m16][2], a[m16][3],
                             b[i][0], b[i][1]);
        }

        if (ch < 7) {
            uint32_t* sa = (uint32_t*)(s + nbuf * XBUFW);
            uint32_t* sb = sa + XCHW;
#pragma unroll
            for (int i = 0; i < 4; i++) {
                const float* ae = (const float*)&av[i];
                const float* be = (const float*)&bv[i];
#pragma unroll
                for (int e = 0; e < 4; e++) {
                    int k = kq * 16 + 4 * i + e;
                    sa[k * XPAD + r] = f2tf32(ae[e]);
                    sb[k * XPAD + r] = f2tf32(be[e]);
                }
            }
            __syncthreads();
        }
    }

    // epilogue: bias + store (float2 per fragment row)
    const float* sbias = s + XBIAS_OFF;
#pragma unroll
    for (int m16 = 0; m16 < 2; m16++) {
        const int row0 = bm * XBM + warp_m + m16 * 16 + g;
#pragma unroll
        for (int i = 0; i < 8; i++) {
            const int col_l = warp_n + i * 8 + 2 * c;
            const float bx = sbias[col_l], by = sbias[col_l + 1];
            float2 v0 = make_float2(d[m16][i][0] + bx, d[m16][i][1] + by);
            float2 v1 = make_float2(d[m16][i][2] + bx, d[m16][i][3] + by);
            *(float2*)(g_xproj + (size_t)row0 * G4 + bn * XBN + col_l) = v0;
            *(float2*)(g_xproj + (size_t)(row0 + 8) * G4 + bn * XBN + col_l) = v1;
        }
    }
}

// =====================================================================
// Kernel 2: forward LSTM recurrence — ROUND-6 EXACT (best: 2094.6us).
// =====================================================================
#define J_STRIDE   560
#define PAR_STRIDE (8 * J_STRIDE)

__device__ __forceinline__ void mbar_wait_cluster(uint32_t mbar, uint32_t parity) {
    asm volatile(
        "{\n\t"
        ".reg .pred P;\n\t"
        "WAIT_%=:\n\t"
        "mbarrier.try_wait.parity.acquire.cluster.shared::cta.b64 P, [%0], %1, 0x989680;\n\t"
        "@P bra DONE_%=;\n\t"
        "bra WAIT_%=;\n\t"
        "DONE_%=:\n\t"
        "}"
        :: "r"(mbar), "r"(parity) : "memory");
}

__global__ void __cluster_dims__(8, 1, 1) __launch_bounds__(256, 1)
lstm_fwd_kernel(const float* __restrict__ whh)
{
    __shared__ __align__(16) unsigned char s_h_raw[2 * PAR_STRIDE];
    __shared__ float s_z[4][128];
    __shared__ __align__(16) float s_xp[2][4][128];
    __shared__ float s_c[4][32];
    __shared__ __align__(16) float s_out[2][4][32];
    __shared__ __align__(8) unsigned long long s_mbar[2];

    const int tid  = threadIdx.x;
    const int j    = blockIdx.x & 7;
    const int cl   = blockIdx.x >> 3;
    const int row  = tid >> 1;
    const int half = tid & 1;

    const int grow = ((row >> 5) << 8) + j * 32 + (row & 31);

    unsigned long long w[64];
    {
        const float* wp = whh + (size_t)grow * Hh + half * 128;
#pragma unroll
        for (int q = 0; q < 32; q++) {
            ulonglong2 v = *(const ulonglong2*)(wp + q * 4);
            w[2*q] = v.x; w[2*q+1] = v.y;
        }
    }

    for (int i = tid; i < 2 * PAR_STRIDE / 4; i += 256) ((float*)s_h_raw)[i] = 0.0f;
    if (tid < 128) s_c[tid >> 5][tid & 31] = 0.0f;

    const uint32_t s_h_addr   = (uint32_t)__cvta_generic_to_shared(&s_h_raw[0]);
    const uint32_t s_xp_addr  = (uint32_t)__cvta_generic_to_shared(&s_xp[0][0][0]);
    const uint32_t s_out_addr = (uint32_t)__cvta_generic_to_shared(&s_out[0][0][0]);
    const uint32_t mbar_addr  = (uint32_t)__cvta_generic_to_shared(&s_mbar[0]);

    if (tid == 0) {
        asm volatile("mbarrier.init.shared.b64 [%0], 1;" :: "r"(mbar_addr) : "memory");
        asm volatile("mbarrier.init.shared.b64 [%0], 1;" :: "r"(mbar_addr + 8) : "memory");
    }

    if (tid < 128) {
        int seg = tid >> 3, off = (tid & 7) * 4;
        int bl = seg >> 2, g = seg & 3;
        const float* src = g_xproj + ((size_t)0 * Bb + cl * 4 + bl) * G4 + g * 256 + j * 32 + off;
        uint32_t dst = s_xp_addr + (uint32_t)((bl * 128) + g * 32 + off) * 4u;
        asm volatile("cp.async.ca.shared.global [%0], [%1], 16;" :: "r"(dst), "l"(src));
    }
    asm volatile("cp.async.commit_group;" ::: "memory");

    __syncthreads();
    asm volatile("barrier.cluster.arrive.aligned;" ::: "memory");
    asm volatile("barrier.cluster.wait.aligned;"   ::: "memory");

    for (int t = 0; t < Tt; t++) {
        const int cur = t & 1, nxt = cur ^ 1;

        if (t > 0) {
            int ph = (t & 1) ? ((t >> 1) & 1) : (((t >> 1) + 1) & 1);
            mbar_wait_cluster(mbar_addr + (uint32_t)cur * 8, (uint32_t)ph);
        }
        if (t < Tt - 1 && tid == 0) {
            asm volatile("mbarrier.arrive.expect_tx.shared.b64 _, [%0], %1;"
                         :: "r"(mbar_addr + (uint32_t)nxt * 8), "r"(4096) : "memory");
        }

        if (tid < 128) {
            int tn = (t + 1 < Tt) ? t + 1 : (Tt - 1);
            int seg = tid >> 3, off = (tid & 7) * 4;
            int bl = seg >> 2, g = seg & 3;
            const float* src = g_xproj + ((size_t)tn * Bb + cl * 4 + bl) * G4 + g * 256 + j * 32 + off;
            uint32_t dst = s_xp_addr + (uint32_t)(((nxt * 4 + bl) * 128) + g * 32 + off) * 4u;
            asm volatile("cp.async.ca.shared.global [%0], [%1], 16;" :: "r"(dst), "l"(src));
        }
        asm volatile("cp.async.commit_group;" ::: "memory");

        unsigned long long acc[4] = {0, 0, 0, 0};
        const unsigned char* hb = s_h_raw + cur * PAR_STRIDE + (half * 4) * J_STRIDE;
#pragma unroll
        for (int q = 0; q < 32; q++) {
            const unsigned char* hq = hb + (q >> 3) * J_STRIDE + (q & 7) * 16;
#pragma unroll
            for (int bl = 0; bl < 4; bl++) {
                ulonglong2 h2 = *(const ulonglong2*)(hq + bl * 128);
                asm("fma.rn.f32x2 %0, %1, %2, %0;" : "+l"(acc[bl]) : "l"(w[2*q]),   "l"(h2.x));
                asm("fma.rn.f32x2 %0, %1, %2, %0;" : "+l"(acc[bl]) : "l"(w[2*q+1]), "l"(h2.y));
            }
        }
        float f[4];
#pragma unroll
        for (int bl = 0; bl < 4; bl++) {
            f[bl] = __uint_as_float((unsigned)acc[bl]) + __uint_as_float((unsigned)(acc[bl] >> 32));
            f[bl] += __shfl_xor_sync(0xffffffffu, f[bl], 1);
        }
        if (half == 0) {
#pragma unroll
            for (int bl = 0; bl < 4; bl++) s_z[bl][row] = f[bl];
        }
        asm volatile("cp.async.wait_group 1;" ::: "memory");
        __syncthreads();

        if (tid < 128) {
            const int bl = tid >> 5, col = tid & 31;
            float zi = s_z[bl][col]       + s_xp[cur][bl][col];
            float zf = s_z[bl][32 + col]  + s_xp[cur][bl][32 + col];
            float zg = s_z[bl][64 + col]  + s_xp[cur][bl][64 + col];
            float zo = s_z[bl][96 + col]  + s_xp[cur][bl][96 + col];
            float c  = sigm(zf) * s_c[bl][col] + sigm(zi) * tanh_fast(zg);
            s_c[bl][col] = c;
            float h  = sigm(zo) * tanh_fast(c);
            s_out[cur][bl][col] = h;
            if (t == Tt - 1)
                g_hf[(cl * 4 + bl) * Hh + j * 32 + col] = h;
        }
        __syncthreads();

        if (t < Tt - 1 && tid < 8) {
            asm volatile("fence.proxy.async.shared::cta;" ::: "memory");
            const int p = tid;
            uint32_t src  = s_out_addr + (uint32_t)(cur * 512);
            uint32_t ldst = s_h_addr + (uint32_t)(nxt * PAR_STRIDE + j * J_STRIDE);
            uint32_t lmb  = mbar_addr + (uint32_t)nxt * 8;
            uint32_t rd, rm;
            asm("mapa.shared::cluster.u32 %0, %1, %2;" : "=r"(rd) : "r"(ldst), "r"(p));
            asm("mapa.shared::cluster.u32 %0, %1, %2;" : "=r"(rm) : "r"(lmb), "r"(p));
            asm volatile(
                "cp.async.bulk.shared::cluster.shared::cta.mbarrier::complete_tx::bytes "
                "[%0], [%1], %2, [%3];"
                :: "r"(rd), "r"(src), "r"(512), "r"(rm) : "memory");
        }
    }
}

// =====================================================================
// Kernel 3: backward LSTM (single step, h=c=0) + fc1(relu) + fc2
// =====================================================================
__global__ __launch_bounds__(256) void head_kernel(
    const int* __restrict__ x,
    const float* __restrict__ emb,
    const float* __restrict__ wihb,
    const float* __restrict__ bihb,
    const float* __restrict__ bhhb,
    const float* __restrict__ fc1w,
    const float* __restrict__ fc1b,
    const float* __restrict__ fc2w,
    const float* __restrict__ fc2b,
    float* __restrict__ out)
{
    __shared__ __align__(16) float s_e[Ee];
    __shared__ float s_lo[2 * Hh];
    __shared__ float s_f1[24];

    const int b = blockIdx.x;
    const int tid = threadIdx.x;

    const int tok = x[b * Tt + (Tt - 1)];
    s_e[tid]  = emb[(size_t)tok * Ee + tid];
    s_lo[tid] = g_hf[b * Hh + tid];
    __syncthreads();

    float zi = bihb[tid]       + bhhb[tid];
    float zg = bihb[512 + tid] + bhhb[512 + tid];
    float zo = bihb[768 + tid] + bhhb[768 + tid];
    const float4* wi = (const float4*)(wihb + (size_t)tid * Ee);
    const float4* wg = (const float4*)(wihb + (size_t)(512 + tid) * Ee);
    const float4* wo = (const float4*)(wihb + (size_t)(768 + tid) * Ee);
    const float4* ev = (const float4*)s_e;
#pragma unroll 4
    for (int q = 0; q < Ee / 4; q++) {
        float4 e4 = ev[q];
        float4 vi = wi[q], vg = wg[q], vo = wo[q];
        zi += vi.x * e4.x + vi.y * e4.y + vi.z * e4.z + vi.w * e4.w;
        zg += vg.x * e4.x + vg.y * e4.y + vg.z * e4.z + vg.w * e4.w;
        zo += vo.x * e4.x + vo.y * e4.y + vo.z * e4.z + vo.w * e4.w;
    }
    float c = sigm(zi) * tanhf(zg);   // c_prev = 0: forget gate drops out
    float h = sigm(zo) * tanhf(c);
    s_lo[Hh + tid] = h;
    __syncthreads();

    if (tid < 24) {
        float s = fc1b[tid];
        const float* w = fc1w + (size_t)tid * (2 * Hh);
#pragma unroll 8
        for (int k = 0; k < 2 * Hh; k++) s = fmaf(w[k], s_lo[k], s);
        s_f1[tid] = fmaxf(s, 0.0f);
    }
    __syncthreads();
    if (tid < Oo) {
        float s = fc2b[tid];
        const float* w = fc2w + (size_t)tid * 24;
#pragma unroll
        for (int k = 0; k < 24; k++) s = fmaf(w[k], s_f1[k], s);
        out[b * Oo + tid] = s;
    }
}

// =====================================================================
// launch
// =====================================================================
extern "C" void kernel_launch(void* const* d_in, const int* in_sizes, int n_in,
                              void* d_out, int out_size)
{
    const int* x           = (const int*)d_in[0];
    const float* emb       = (const float*)d_in[1];
    const float* w_ih_f    = (const float*)d_in[2];
    const float* w_hh_f    = (const float*)d_in[3];
    const float* b_ih_f    = (const float*)d_in[4];
    const float* b_hh_f    = (const float*)d_in[5];
    const float* w_ih_b    = (const float*)d_in[6];
    // d_in[7] = w_hh_b (unused: backward dir is a single step from h=0)
    const float* b_ih_b    = (const float*)d_in[8];
    const float* b_hh_b    = (const float*)d_in[9];
    const float* fc1_w     = (const float*)d_in[10];
    const float* fc1_b     = (const float*)d_in[11];
    const float* fc2_w     = (const float*)d_in[12];
    const float* fc2_b     = (const float*)d_in[13];
    float* out             = (float*)d_out;

    static bool attr_set = false;
    if (!attr_set) {
        cudaFuncSetAttribute(xproj_mma_kernel,
                             cudaFuncAttributeMaxDynamicSharedMemorySize, XSMEM_BYTES);
        attr_set = true;
    }

    dim3 xgrid(Tt * Bb / XBM, G4 / XBN);   // (256, 8)
    xproj_mma_kernel<<<xgrid, 256, XSMEM_BYTES>>>(x, emb, w_ih_f, b_ih_f, b_hh_f);

    lstm_fwd_kernel<<<128, 256>>>(w_hh_f);

    head_kernel<<<Bb, 256>>>(x, emb, w_ih_b, b_ih_b, b_hh_b,
                             fc1_w, fc1_b, fc2_w, fc2_b, out);
}

// round 12
// speedup vs baseline: 1.4850x; 1.0252x over previous
#include <cuda_runtime.h>
#include <cuda_bf16.h>
#include <cstdint>

// ---------------- problem constants ----------------
#define Bb   64
#define Tt   512
#define Ee   256
#define Hh   256
#define G4   1024          // 4*H
#define Oo   2

// ---------------- scratch (device globals: no runtime alloc) ----------------
__device__ float g_xproj[(size_t)Tt * Bb * G4];   // [t][b][gate] fp32, 128MB
__device__ float g_hf[Bb * Hh];                   // final forward hidden

__device__ __forceinline__ float sigm(float x) {
    return __fdividef(1.0f, 1.0f + __expf(-x));
}
__device__ __forceinline__ float tanh_mufu(float x) {
    float r;
    asm("tanh.approx.f32 %0, %1;" : "=f"(r) : "f"(x));
    return r;
}
__device__ __forceinline__ float sigm_mufu(float x) {
    return fmaf(tanh_mufu(0.5f * x), 0.5f, 0.5f);
}

// =====================================================================
// Kernel 1: xproj = emb[x] @ W_ih_f^T + bias via mma.sync tf32
// (round-11 exact: 185.6us, tensor pipe)
// =====================================================================
#define XBM 128
#define XBN 128
#define XBK 32
#define XPAD 136
#define XCHW (XBK * XPAD)
#define XBUFW (2 * XCHW)
#define XBIAS_OFF (2 * XBUFW)
#define XSMEM_BYTES ((XBIAS_OFF + XBN) * 4)

__device__ __forceinline__ uint32_t f2tf32(float v) {
    uint32_t r;
    asm("cvt.rna.tf32.f32 %0, %1;" : "=r"(r) : "f"(v));
    return r;
}

__device__ __forceinline__ void mma_tf32(
    float& d0, float& d1, float& d2, float& d3,
    uint32_t a0, uint32_t a1, uint32_t a2, uint32_t a3,
    uint32_t b0, uint32_t b1)
{
    asm volatile(
        "mma.sync.aligned.m16n8k8.row.col.f32.tf32.tf32.f32 "
        "{%0,%1,%2,%3}, {%4,%5,%6,%7}, {%8,%9}, {%0,%1,%2,%3};"
        : "+f"(d0), "+f"(d1), "+f"(d2), "+f"(d3)
        : "r"(a0), "r"(a1), "r"(a2), "r"(a3), "r"(b0), "r"(b1));
}

__global__ void __launch_bounds__(256, 1) xproj_mma_kernel(
    const int* __restrict__ x,
    const float* __restrict__ emb,
    const float* __restrict__ wih,
    const float* __restrict__ bih,
    const float* __restrict__ bhh)
{
    extern __shared__ __align__(16) float s[];
    const int tid  = threadIdx.x;
    const int wid  = tid >> 5;
    const int lane = tid & 31;
    const int g    = lane >> 2;
    const int c    = lane & 3;
    const int bm   = blockIdx.x;
    const int bn   = blockIdx.y;
    const int warp_m = (wid >> 1) * 32;
    const int warp_n = (wid & 1) * 64;

    const int r  = tid >> 1;
    const int kq = tid & 1;
    const int m  = bm * XBM + r;
    const int tok = x[(m & 63) * Tt + (m >> 6)];
    const float* aptr = emb + (size_t)tok * Ee + kq * 16;
    const float* bptr = wih + (size_t)(bn * XBN + r) * Ee + kq * 16;

    if (tid < XBN)
        s[XBIAS_OFF + tid] = bih[bn * XBN + tid] + bhh[bn * XBN + tid];

    float d[2][8][4];
#pragma unroll
    for (int i = 0; i < 2; i++)
#pragma unroll
        for (int n = 0; n < 8; n++)
#pragma unroll
            for (int e = 0; e < 4; e++) d[i][n][e] = 0.0f;

    float4 av[4], bv[4];

#pragma unroll
    for (int i = 0; i < 4; i++) {
        av[i] = *(const float4*)(aptr + 4 * i);
        bv[i] = *(const float4*)(bptr + 4 * i);
    }
    {
        uint32_t* sa = (uint32_t*)s;
        uint32_t* sb = (uint32_t*)(s + XCHW);
#pragma unroll
        for (int i = 0; i < 4; i++) {
            const float* ae = (const float*)&av[i];
            const float* be = (const float*)&bv[i];
#pragma unroll
            for (int e = 0; e < 4; e++) {
                int k = kq * 16 + 4 * i + e;
                sa[k * XPAD + r] = f2tf32(ae[e]);
                sb[k * XPAD + r] = f2tf32(be[e]);
            }
        }
    }
    __syncthreads();

    for (int ch = 0; ch < 8; ch++) {
        const int buf = ch & 1, nbuf = buf ^ 1;

        if (ch < 7) {
#pragma unroll
            for (int i = 0; i < 4; i++) {
                av[i] = *(const float4*)(aptr + (ch + 1) * XBK + 4 * i);
                bv[i] = *(const float4*)(bptr + (ch + 1) * XBK + 4 * i);
            }
        }

        const uint32_t* As = (const uint32_t*)(s + buf * XBUFW);
        const uint32_t* Bs = As + XCHW;
#pragma unroll
        for (int ks = 0; ks < 4; ks++) {
            const int kr0 = (ks * 8 + c) * XPAD;
            const int kr1 = (ks * 8 + c + 4) * XPAD;
            uint32_t a[2][4];
#pragma unroll
            for (int m16 = 0; m16 < 2; m16++) {
                const int rr = warp_m + m16 * 16 + g;
                a[m16][0] = As[kr0 + rr];
                a[m16][1] = As[kr0 + rr + 8];
                a[m16][2] = As[kr1 + rr];
                a[m16][3] = As[kr1 + rr + 8];
            }
            uint32_t b[8][2];
#pragma unroll
            for (int i = 0; i < 8; i++) {
                const int nn = warp_n + i * 8 + g;
                b[i][0] = Bs[kr0 + nn];
                b[i][1] = Bs[kr1 + nn];
            }
#pragma unroll
            for (int m16 = 0; m16 < 2; m16++)
#pragma unroll
                for (int i = 0; i < 8; i++)
                    mma_tf32(d[m16][i][0], d[m16][i][1], d[m16][i][2], d[m16][i][3],
                             a[m16][0], a[m16][1], a[m16][2], a[m16][3],
                             b[i][0], b[i][1]);
        }

        if (ch < 7) {
            uint32_t* sa = (uint32_t*)(s + nbuf * XBUFW);
            uint32_t* sb = sa + XCHW;
#pragma unroll
            for (int i = 0; i < 4; i++) {
                const float* ae = (const float*)&av[i];
                const float* be = (const float*)&bv[i];
#pragma unroll
                for (int e = 0; e < 4; e++) {
                    int k = kq * 16 + 4 * i + e;
                    sa[k * XPAD + r] = f2tf32(ae[e]);
                    sb[k * XPAD + r] = f2tf32(be[e]);
                }
            }
            __syncthreads();
        }
    }

    const float* sbias = s + XBIAS_OFF;
#pragma unroll
    for (int m16 = 0; m16 < 2; m16++) {
        const int row0 = bm * XBM + warp_m + m16 * 16 + g;
#pragma unroll
        for (int i = 0; i < 8; i++) {
            const int col_l = warp_n + i * 8 + 2 * c;
            const float bx = sbias[col_l], by = sbias[col_l + 1];
            float2 v0 = make_float2(d[m16][i][0] + bx, d[m16][i][1] + by);
            float2 v1 = make_float2(d[m16][i][2] + bx, d[m16][i][3] + by);
            *(float2*)(g_xproj + (size_t)row0 * G4 + bn * XBN + col_l) = v0;
            *(float2*)(g_xproj + (size_t)(row0 + 8) * G4 + bn * XBN + col_l) = v1;
        }
    }
}

// =====================================================================
// Kernel 2: forward LSTM recurrence (r6 base + MUFU.TANH gates +
// asymmetric barriers: FMA warps arrive-only, gate-only staging bar).
// =====================================================================
#define J_STRIDE   560
#define PAR_STRIDE (8 * J_STRIDE)

__device__ __forceinline__ void mbar_wait_cluster(uint32_t mbar, uint32_t parity) {
    asm volatile(
        "{\n\t"
        ".reg .pred P;\n\t"
        "WAIT_%=:\n\t"
        "mbarrier.try_wait.parity.acquire.cluster.shared::cta.b64 P, [%0], %1, 0x989680;\n\t"
        "@P bra DONE_%=;\n\t"
        "bra WAIT_%=;\n\t"
        "DONE_%=:\n\t"
        "}"
        :: "r"(mbar), "r"(parity) : "memory");
}

__global__ void __cluster_dims__(8, 1, 1) __launch_bounds__(256, 1)
lstm_fwd_kernel(const float* __restrict__ whh)
{
    __shared__ __align__(16) unsigned char s_h_raw[2 * PAR_STRIDE];
    __shared__ float s_z[4][128];
    __shared__ __align__(16) float s_xp[2][4][128];
    __shared__ float s_c[4][32];
    __shared__ __align__(16) float s_out[2][4][32];
    __shared__ __align__(8) unsigned long long s_mbar[2];

    const int tid  = threadIdx.x;
    const int j    = blockIdx.x & 7;
    const int cl   = blockIdx.x >> 3;
    const int row  = tid >> 1;
    const int half = tid & 1;

    const int grow = ((row >> 5) << 8) + j * 32 + (row & 31);

    unsigned long long w[64];
    {
        const float* wp = whh + (size_t)grow * Hh + half * 128;
#pragma unroll
        for (int q = 0; q < 32; q++) {
            ulonglong2 v = *(const ulonglong2*)(wp + q * 4);
            w[2*q] = v.x; w[2*q+1] = v.y;
        }
    }

    for (int i = tid; i < 2 * PAR_STRIDE / 4; i += 256) ((float*)s_h_raw)[i] = 0.0f;
    if (tid < 128) s_c[tid >> 5][tid & 31] = 0.0f;

    const uint32_t s_h_addr   = (uint32_t)__cvta_generic_to_shared(&s_h_raw[0]);
    const uint32_t s_xp_addr  = (uint32_t)__cvta_generic_to_shared(&s_xp[0][0][0]);
    const uint32_t s_out_addr = (uint32_t)__cvta_generic_to_shared(&s_out[0][0][0]);
    const uint32_t mbar_addr  = (uint32_t)__cvta_generic_to_shared(&s_mbar[0]);

    if (tid == 0) {
        asm volatile("mbarrier.init.shared.b64 [%0], 1;" :: "r"(mbar_addr) : "memory");
        asm volatile("mbarrier.init.shared.b64 [%0], 1;" :: "r"(mbar_addr + 8) : "memory");
    }

    if (tid < 128) {
        int seg = tid >> 3, off = (tid & 7) * 4;
        int bl = seg >> 2, g = seg & 3;
        const float* src = g_xproj + ((size_t)0 * Bb + cl * 4 + bl) * G4 + g * 256 + j * 32 + off;
        uint32_t dst = s_xp_addr + (uint32_t)((bl * 128) + g * 32 + off) * 4u;
        asm volatile("cp.async.ca.shared.global [%0], [%1], 16;" :: "r"(dst), "l"(src));
        asm volatile("cp.async.commit_group;" ::: "memory");
    }

    __syncthreads();
    asm volatile("barrier.cluster.arrive.aligned;" ::: "memory");
    asm volatile("barrier.cluster.wait.aligned;"   ::: "memory");

    for (int t = 0; t < Tt; t++) {
        const int cur = t & 1, nxt = cur ^ 1;

        if (t > 0) {
            int ph = (t & 1) ? ((t >> 1) & 1) : (((t >> 1) + 1) & 1);
            mbar_wait_cluster(mbar_addr + (uint32_t)cur * 8, (uint32_t)ph);
        }
        if (t < Tt - 1 && tid == 0) {
            asm volatile("mbarrier.arrive.expect_tx.shared.b64 _, [%0], %1;"
                         :: "r"(mbar_addr + (uint32_t)nxt * 8), "r"(4096) : "memory");
        }

        // prefetch next step's xproj slice (gate warps only)
        if (tid < 128) {
            int tn = (t + 1 < Tt) ? t + 1 : (Tt - 1);
            int seg = tid >> 3, off = (tid & 7) * 4;
            int bl = seg >> 2, g = seg & 3;
            const float* src = g_xproj + ((size_t)tn * Bb + cl * 4 + bl) * G4 + g * 256 + j * 32 + off;
            uint32_t dst = s_xp_addr + (uint32_t)(((nxt * 4 + bl) * 128) + g * 32 + off) * 4u;
            asm volatile("cp.async.ca.shared.global [%0], [%1], 16;" :: "r"(dst), "l"(src));
            asm volatile("cp.async.commit_group;" ::: "memory");
        }

        // ---- Whh @ h (all 8 warps) ----
        unsigned long long acc[4] = {0, 0, 0, 0};
        const unsigned char* hb = s_h_raw + cur * PAR_STRIDE + (half * 4) * J_STRIDE;
#pragma unroll
        for (int q = 0; q < 32; q++) {
            const unsigned char* hq = hb + (q >> 3) * J_STRIDE + (q & 7) * 16;
#pragma unroll
            for (int bl = 0; bl < 4; bl++) {
                ulonglong2 h2 = *(const ulonglong2*)(hq + bl * 128);
                asm("fma.rn.f32x2 %0, %1, %2, %0;" : "+l"(acc[bl]) : "l"(w[2*q]),   "l"(h2.x));
                asm("fma.rn.f32x2 %0, %1, %2, %0;" : "+l"(acc[bl]) : "l"(w[2*q+1]), "l"(h2.y));
            }
        }
        float f[4];
#pragma unroll
        for (int bl = 0; bl < 4; bl++) {
            f[bl] = __uint_as_float((unsigned)acc[bl]) + __uint_as_float((unsigned)(acc[bl] >> 32));
            f[bl] += __shfl_xor_sync(0xffffffffu, f[bl], 1);
        }
        if (half == 0) {
#pragma unroll
            for (int bl = 0; bl < 4; bl++) s_z[bl][row] = f[bl];
        }

        if (tid < 128) {
            // gate warps: converge on s_z, then compute gates and send
            asm volatile("bar.sync 1, 256;" ::: "memory");
            asm volatile("cp.async.wait_group 1;" ::: "memory");

            const int bl = tid >> 5, col = tid & 31;
            float zi = s_z[bl][col]       + s_xp[cur][bl][col];
            float zf = s_z[bl][32 + col]  + s_xp[cur][bl][32 + col];
            float zg = s_z[bl][64 + col]  + s_xp[cur][bl][64 + col];
            float zo = s_z[bl][96 + col]  + s_xp[cur][bl][96 + col];
            float c  = sigm_mufu(zf) * s_c[bl][col] + sigm_mufu(zi) * tanh_mufu(zg);
            s_c[bl][col] = c;
            float h  = sigm_mufu(zo) * tanh_mufu(c);
            s_out[cur][bl][col] = h;
            if (t == Tt - 1)
                g_hf[(cl * 4 + bl) * Hh + j * 32 + col] = h;

            asm volatile("bar.sync 2, 128;" ::: "memory");

            if (t < Tt - 1 && tid < 8) {
                asm volatile("fence.proxy.async.shared::cta;" ::: "memory");
                const int p = tid;
                uint32_t src  = s_out_addr + (uint32_t)(cur * 512);
                uint32_t ldst = s_h_addr + (uint32_t)(nxt * PAR_STRIDE + j * J_STRIDE);
                uint32_t lmb  = mbar_addr + (uint32_t)nxt * 8;
                uint32_t rd, rm;
                asm("mapa.shared::cluster.u32 %0, %1, %2;" : "=r"(rd) : "r"(ldst), "r"(p));
                asm("mapa.shared::cluster.u32 %0, %1, %2;" : "=r"(rm) : "r"(lmb), "r"(p));
                asm volatile(
                    "cp.async.bulk.shared::cluster.shared::cta.mbarrier::complete_tx::bytes "
                    "[%0], [%1], %2, [%3];"
                    :: "r"(rd), "r"(src), "r"(512), "r"(rm) : "memory");
            }
        } else {
            // FMA-only warps: signal s_z done, skip straight to next wait.
            // Safe: s_z(t+1) writes are gated by mbar[t+1] ⊇ own send(t)
            // ⊇ gate warps' s_z(t) reads.
            asm volatile("bar.arrive 1, 256;" ::: "memory");
        }
    }
}

// =====================================================================
// Kernel 3: backward LSTM (single step, h=c=0) + fc1(relu) + fc2
// =====================================================================
__global__ __launch_bounds__(256) void head_kernel(
    const int* __restrict__ x,
    const float* __restrict__ emb,
    const float* __restrict__ wihb,
    const float* __restrict__ bihb,
    const float* __restrict__ bhhb,
    const float* __restrict__ fc1w,
    const float* __restrict__ fc1b,
    const float* __restrict__ fc2w,
    const float* __restrict__ fc2b,
    float* __restrict__ out)
{
    __shared__ __align__(16) float s_e[Ee];
    __shared__ float s_lo[2 * Hh];
    __shared__ float s_f1[24];

    const int b = blockIdx.x;
    const int tid = threadIdx.x;

    const int tok = x[b * Tt + (Tt - 1)];
    s_e[tid]  = emb[(size_t)tok * Ee + tid];
    s_lo[tid] = g_hf[b * Hh + tid];
    __syncthreads();

    float zi = bihb[tid]       + bhhb[tid];
    float zg = bihb[512 + tid] + bhhb[512 + tid];
    float zo = bihb[768 + tid] + bhhb[768 + tid];
    const float4* wi = (const float4*)(wihb + (size_t)tid * Ee);
    const float4* wg = (const float4*)(wihb + (size_t)(512 + tid) * Ee);
    const float4* wo = (const float4*)(wihb + (size_t)(768 + tid) * Ee);
    const float4* ev = (const float4*)s_e;
#pragma unroll 4
    for (int q = 0; q < Ee / 4; q++) {
        float4 e4 = ev[q];
        float4 vi = wi[q], vg = wg[q], vo = wo[q];
        zi += vi.x * e4.x + vi.y * e4.y + vi.z * e4.z + vi.w * e4.w;
        zg += vg.x * e4.x + vg.y * e4.y + vg.z * e4.z + vg.w * e4.w;
        zo += vo.x * e4.x + vo.y * e4.y + vo.z * e4.z + vo.w * e4.w;
    }
    float c = sigm(zi) * tanhf(zg);   // c_prev = 0: forget gate drops out
    float h = sigm(zo) * tanhf(c);
    s_lo[Hh + tid] = h;
    __syncthreads();

    if (tid < 24) {
        float s = fc1b[tid];
        const float* w = fc1w + (size_t)tid * (2 * Hh);
#pragma unroll 8
        for (int k = 0; k < 2 * Hh; k++) s = fmaf(w[k], s_lo[k], s);
        s_f1[tid] = fmaxf(s, 0.0f);
    }
    __syncthreads();
    if (tid < Oo) {
        float s = fc2b[tid];
        const float* w = fc2w + (size_t)tid * 24;
#pragma unroll
        for (int k = 0; k < 24; k++) s = fmaf(w[k], s_f1[k], s);
        out[b * Oo + tid] = s;
    }
}

// =====================================================================
// launch
// =====================================================================
extern "C" void kernel_launch(void* const* d_in, const int* in_sizes, int n_in,
                              void* d_out, int out_size)
{
    const int* x           = (const int*)d_in[0];
    const float* emb       = (const float*)d_in[1];
    const float* w_ih_f    = (const float*)d_in[2];
    const float* w_hh_f    = (const float*)d_in[3];
    const float* b_ih_f    = (const float*)d_in[4];
    const float* b_hh_f    = (const float*)d_in[5];
    const float* w_ih_b    = (const float*)d_in[6];
    // d_in[7] = w_hh_b (unused: backward dir is a single step from h=0)
    const float* b_ih_b    = (const float*)d_in[8];
    const float* b_hh_b    = (const float*)d_in[9];
    const float* fc1_w     = (const float*)d_in[10];
    const float* fc1_b     = (const float*)d_in[11];
    const float* fc2_w     = (const float*)d_in[12];
    const float* fc2_b     = (const float*)d_in[13];
    float* out             = (float*)d_out;

    static bool attr_set = false;
    if (!attr_set) {
        cudaFuncSetAttribute(xproj_mma_kernel,
                             cudaFuncAttributeMaxDynamicSharedMemorySize, XSMEM_BYTES);
        attr_set = true;
    }

    dim3 xgrid(Tt * Bb / XBM, G4 / XBN);   // (256, 8)
    xproj_mma_kernel<<<xgrid, 256, XSMEM_BYTES>>>(x, emb, w_ih_f, b_ih_f, b_hh_f);

    lstm_fwd_kernel<<<128, 256>>>(w_hh_f);

    head_kernel<<<Bb, 256>>>(x, emb, w_ih_b, b_ih_b, b_hh_b,
                             fc1_w, fc1_b, fc2_w, fc2_b, out);
}

// round 13
// speedup vs baseline: 1.7382x; 1.1705x over previous
#include <cuda_runtime.h>
#include <cuda_bf16.h>
#include <cstdint>

// ---------------- problem constants ----------------
#define Bb   64
#define Tt   512
#define Ee   256
#define Hh   256
#define G4   1024          // 4*H
#define Oo   2

// ---------------- scratch (device globals: no runtime alloc) ----------------
__device__ float g_xproj[(size_t)Tt * Bb * G4];   // [t][b][gate] fp32, 128MB
__device__ float g_hf[Bb * Hh];                   // final forward hidden

__device__ __forceinline__ float sigm(float x) {
    return __fdividef(1.0f, 1.0f + __expf(-x));
}
__device__ __forceinline__ float tanh_mufu(float x) {
    float r;
    asm("tanh.approx.f32 %0, %1;" : "=f"(r) : "f"(x));
    return r;
}
__device__ __forceinline__ float sigm_mufu(float x) {
    return fmaf(tanh_mufu(0.5f * x), 0.5f, 0.5f);
}

// =====================================================================
// Kernel 1: xproj = emb[x] @ W_ih_f^T + bias via mma.sync tf32
// (round-11 exact: 185.6us)
// =====================================================================
#define XBM 128
#define XBN 128
#define XBK 32
#define XPAD 136
#define XCHW (XBK * XPAD)
#define XBUFW (2 * XCHW)
#define XBIAS_OFF (2 * XBUFW)
#define XSMEM_BYTES ((XBIAS_OFF + XBN) * 4)

__device__ __forceinline__ uint32_t f2tf32(float v) {
    uint32_t r;
    asm("cvt.rna.tf32.f32 %0, %1;" : "=r"(r) : "f"(v));
    return r;
}

__device__ __forceinline__ void mma_tf32(
    float& d0, float& d1, float& d2, float& d3,
    uint32_t a0, uint32_t a1, uint32_t a2, uint32_t a3,
    uint32_t b0, uint32_t b1)
{
    asm volatile(
        "mma.sync.aligned.m16n8k8.row.col.f32.tf32.tf32.f32 "
        "{%0,%1,%2,%3}, {%4,%5,%6,%7}, {%8,%9}, {%0,%1,%2,%3};"
        : "+f"(d0), "+f"(d1), "+f"(d2), "+f"(d3)
        : "r"(a0), "r"(a1), "r"(a2), "r"(a3), "r"(b0), "r"(b1));
}

__global__ void __launch_bounds__(256, 1) xproj_mma_kernel(
    const int* __restrict__ x,
    const float* __restrict__ emb,
    const float* __restrict__ wih,
    const float* __restrict__ bih,
    const float* __restrict__ bhh)
{
    extern __shared__ __align__(16) float s[];
    const int tid  = threadIdx.x;
    const int wid  = tid >> 5;
    const int lane = tid & 31;
    const int g    = lane >> 2;
    const int c    = lane & 3;
    const int bm   = blockIdx.x;
    const int bn   = blockIdx.y;
    const int warp_m = (wid >> 1) * 32;
    const int warp_n = (wid & 1) * 64;

    const int r  = tid >> 1;
    const int kq = tid & 1;
    const int m  = bm * XBM + r;
    const int tok = x[(m & 63) * Tt + (m >> 6)];
    const float* aptr = emb + (size_t)tok * Ee + kq * 16;
    const float* bptr = wih + (size_t)(bn * XBN + r) * Ee + kq * 16;

    if (tid < XBN)
        s[XBIAS_OFF + tid] = bih[bn * XBN + tid] + bhh[bn * XBN + tid];

    float d[2][8][4];
#pragma unroll
    for (int i = 0; i < 2; i++)
#pragma unroll
        for (int n = 0; n < 8; n++)
#pragma unroll
            for (int e = 0; e < 4; e++) d[i][n][e] = 0.0f;

    float4 av[4], bv[4];

#pragma unroll
    for (int i = 0; i < 4; i++) {
        av[i] = *(const float4*)(aptr + 4 * i);
        bv[i] = *(const float4*)(bptr + 4 * i);
    }
    {
        uint32_t* sa = (uint32_t*)s;
        uint32_t* sb = (uint32_t*)(s + XCHW);
#pragma unroll
        for (int i = 0; i < 4; i++) {
            const float* ae = (const float*)&av[i];
            const float* be = (const float*)&bv[i];
#pragma unroll
            for (int e = 0; e < 4; e++) {
                int k = kq * 16 + 4 * i + e;
                sa[k * XPAD + r] = f2tf32(ae[e]);
                sb[k * XPAD + r] = f2tf32(be[e]);
            }
        }
    }
    __syncthreads();

    for (int ch = 0; ch < 8; ch++) {
        const int buf = ch & 1, nbuf = buf ^ 1;

        if (ch < 7) {
#pragma unroll
            for (int i = 0; i < 4; i++) {
                av[i] = *(const float4*)(aptr + (ch + 1) * XBK + 4 * i);
                bv[i] = *(const float4*)(bptr + (ch + 1) * XBK + 4 * i);
            }
        }

        const uint32_t* As = (const uint32_t*)(s + buf * XBUFW);
        const uint32_t* Bs = As + XCHW;
#pragma unroll
        for (int ks = 0; ks < 4; ks++) {
            const int kr0 = (ks * 8 + c) * XPAD;
            const int kr1 = (ks * 8 + c + 4) * XPAD;
            uint32_t a[2][4];
#pragma unroll
            for (int m16 = 0; m16 < 2; m16++) {
                const int rr = warp_m + m16 * 16 + g;
                a[m16][0] = As[kr0 + rr];
                a[m16][1] = As[kr0 + rr + 8];
                a[m16][2] = As[kr1 + rr];
                a[m16][3] = As[kr1 + rr + 8];
            }
            uint32_t b[8][2];
#pragma unroll
            for (int i = 0; i < 8; i++) {
                const int nn = warp_n + i * 8 + g;
                b[i][0] = Bs[kr0 + nn];
                b[i][1] = Bs[kr1 + nn];
            }
#pragma unroll
            for (int m16 = 0; m16 < 2; m16++)
#pragma unroll
                for (int i = 0; i < 8; i++)
                    mma_tf32(d[m16][i][0], d[m16][i][1], d[m16][i][2], d[m16][i][3],
                             a[m16][0], a[m16][1], a[m16][2], a[m16][3],
                             b[i][0], b[i][1]);
        }

        if (ch < 7) {
            uint32_t* sa = (uint32_t*)(s + nbuf * XBUFW);
            uint32_t* sb = sa + XCHW;
#pragma unroll
            for (int i = 0; i < 4; i++) {
                const float* ae = (const float*)&av[i];
                const float* be = (const float*)&bv[i];
#pragma unroll
                for (int e = 0; e < 4; e++) {
                    int k = kq * 16 + 4 * i + e;
                    sa[k * XPAD + r] = f2tf32(ae[e]);
                    sb[k * XPAD + r] = f2tf32(be[e]);
                }
            }
            __syncthreads();
        }
    }

    const float* sbias = s + XBIAS_OFF;
#pragma unroll
    for (int m16 = 0; m16 < 2; m16++) {
        const int row0 = bm * XBM + warp_m + m16 * 16 + g;
#pragma unroll
        for (int i = 0; i < 8; i++) {
            const int col_l = warp_n + i * 8 + 2 * c;
            const float bx = sbias[col_l], by = sbias[col_l + 1];
            float2 v0 = make_float2(d[m16][i][0] + bx, d[m16][i][1] + by);
            float2 v1 = make_float2(d[m16][i][2] + bx, d[m16][i][3] + by);
            *(float2*)(g_xproj + (size_t)row0 * G4 + bn * XBN + col_l) = v0;
            *(float2*)(g_xproj + (size_t)(row0 + 8) * G4 + bn * XBN + col_l) = v1;
        }
    }
}

// =====================================================================
// Kernel 2: forward LSTM recurrence — CLUSTER-4 version.
// 32 clusters x 4 CTAs, 512 thr/CTA; CTA owns 64 h-cols (256 gate rows),
// 2 batches/cluster; thread = (row, k-half) -> 64 weight regs.
// Exchange: 4x 512B bulk push + complete_tx; MUFU gates; asym barriers.
// =====================================================================
#define J_STRIDE   544               // bytes per src-CTA h block (512 used + pad)
#define PAR_STRIDE (4 * J_STRIDE)    // 2176

__device__ __forceinline__ void mbar_wait_cluster(uint32_t mbar, uint32_t parity) {
    asm volatile(
        "{\n\t"
        ".reg .pred P;\n\t"
        "WAIT_%=:\n\t"
        "mbarrier.try_wait.parity.acquire.cluster.shared::cta.b64 P, [%0], %1, 0x989680;\n\t"
        "@P bra DONE_%=;\n\t"
        "bra WAIT_%=;\n\t"
        "DONE_%=:\n\t"
        "}"
        :: "r"(mbar), "r"(parity) : "memory");
}

__global__ void __cluster_dims__(4, 1, 1) __launch_bounds__(512, 1)
lstm_fwd_kernel(const float* __restrict__ whh)
{
    __shared__ __align__(16) unsigned char s_h_raw[2 * PAR_STRIDE];
    __shared__ float s_z[2][256];                     // [batch][row]
    __shared__ __align__(16) float s_xp[2][2][256];   // [parity][batch][gate*64+col]
    __shared__ float s_c[2][64];
    __shared__ __align__(16) float s_out[2][2][64];   // [parity][batch][col]
    __shared__ __align__(8) unsigned long long s_mbar[2];

    const int tid  = threadIdx.x;                     // 0..511
    const int j    = blockIdx.x & 3;                  // cluster rank
    const int cl   = blockIdx.x >> 2;                 // batch group (0..31)
    const int row  = tid >> 1;                        // 0..255 (own gate row)
    const int half = tid & 1;                         // k half

    // global gate row: gate = row>>6, col = j*64 + (row&63)
    const int grow = ((row >> 6) << 8) + j * 64 + (row & 63);

    // 128 weights (own half of k) as 64 packed f32x2 regs
    unsigned long long w[64];
    {
        const float* wp = whh + (size_t)grow * Hh + half * 128;
#pragma unroll
        for (int q = 0; q < 32; q++) {
            ulonglong2 v = *(const ulonglong2*)(wp + q * 4);
            w[2*q] = v.x; w[2*q+1] = v.y;
        }
    }

    // init
    for (int i = tid; i < 2 * PAR_STRIDE / 4; i += 512) ((float*)s_h_raw)[i] = 0.0f;
    if (tid < 128) s_c[tid >> 6][tid & 63] = 0.0f;

    const uint32_t s_h_addr   = (uint32_t)__cvta_generic_to_shared(&s_h_raw[0]);
    const uint32_t s_xp_addr  = (uint32_t)__cvta_generic_to_shared(&s_xp[0][0][0]);
    const uint32_t s_out_addr = (uint32_t)__cvta_generic_to_shared(&s_out[0][0][0]);
    const uint32_t mbar_addr  = (uint32_t)__cvta_generic_to_shared(&s_mbar[0]);

    if (tid == 0) {
        asm volatile("mbarrier.init.shared.b64 [%0], 1;" :: "r"(mbar_addr) : "memory");
        asm volatile("mbarrier.init.shared.b64 [%0], 1;" :: "r"(mbar_addr + 8) : "memory");
    }

    // prefetch xproj slice for t=0 into parity 0 (128 threads x 16B)
    if (tid < 128) {
        int bl = tid >> 6, u = tid & 63;
        int gate = u >> 4, col4 = (u & 15) * 4;
        const float* src = g_xproj + ((size_t)0 * Bb + cl * 2 + bl) * G4
                           + gate * 256 + j * 64 + col4;
        uint32_t dst = s_xp_addr + (uint32_t)((bl * 256) + u * 4) * 4u;
        asm volatile("cp.async.ca.shared.global [%0], [%1], 16;" :: "r"(dst), "l"(src));
        asm volatile("cp.async.commit_group;" ::: "memory");
    }

    __syncthreads();
    asm volatile("barrier.cluster.arrive.aligned;" ::: "memory");
    asm volatile("barrier.cluster.wait.aligned;"   ::: "memory");

    for (int t = 0; t < Tt; t++) {
        const int cur = t & 1, nxt = cur ^ 1;

        if (t > 0) {
            int ph = (t & 1) ? ((t >> 1) & 1) : (((t >> 1) + 1) & 1);
            mbar_wait_cluster(mbar_addr + (uint32_t)cur * 8, (uint32_t)ph);
        }
        if (t < Tt - 1 && tid == 0) {
            asm volatile("mbarrier.arrive.expect_tx.shared.b64 _, [%0], %1;"
                         :: "r"(mbar_addr + (uint32_t)nxt * 8), "r"(2048) : "memory");
        }

        // prefetch next step's xproj slice (gate warps only)
        if (tid < 128) {
            int tn = (t + 1 < Tt) ? t + 1 : (Tt - 1);
            int bl = tid >> 6, u = tid & 63;
            int gate = u >> 4, col4 = (u & 15) * 4;
            const float* src = g_xproj + ((size_t)tn * Bb + cl * 2 + bl) * G4
                               + gate * 256 + j * 64 + col4;
            uint32_t dst = s_xp_addr + (uint32_t)(((nxt * 2 + bl) * 256) + u * 4) * 4u;
            asm volatile("cp.async.ca.shared.global [%0], [%1], 16;" :: "r"(dst), "l"(src));
            asm volatile("cp.async.commit_group;" ::: "memory");
        }

        // ---- Whh @ h: thread = (row, k-half), 2 batches ----
        // half h covers k in [half*128, half*128+128) = src blocks {2*half, 2*half+1}
        unsigned long long acc[2] = {0, 0};
        const unsigned char* hb = s_h_raw + cur * PAR_STRIDE + (half * 2) * J_STRIDE;
#pragma unroll
        for (int sblk = 0; sblk < 2; sblk++) {
#pragma unroll
            for (int q = 0; q < 16; q++) {
                const unsigned char* hq = hb + sblk * J_STRIDE + q * 16;
#pragma unroll
                for (int bl = 0; bl < 2; bl++) {
                    ulonglong2 h2 = *(const ulonglong2*)(hq + bl * 256);
                    int wi = 2 * (sblk * 16 + q);
                    asm("fma.rn.f32x2 %0, %1, %2, %0;" : "+l"(acc[bl]) : "l"(w[wi]),   "l"(h2.x));
                    asm("fma.rn.f32x2 %0, %1, %2, %0;" : "+l"(acc[bl]) : "l"(w[wi+1]), "l"(h2.y));
                }
            }
        }
        float f[2];
#pragma unroll
        for (int bl = 0; bl < 2; bl++) {
            f[bl] = __uint_as_float((unsigned)acc[bl]) + __uint_as_float((unsigned)(acc[bl] >> 32));
            f[bl] += __shfl_xor_sync(0xffffffffu, f[bl], 1);
        }
        if (half == 0) {
#pragma unroll
            for (int bl = 0; bl < 2; bl++) s_z[bl][row] = f[bl];
        }

        if (tid < 128) {
            asm volatile("bar.sync 1, 512;" ::: "memory");
            asm volatile("cp.async.wait_group 1;" ::: "memory");

            const int bl = tid >> 6, col = tid & 63;
            float zi = s_z[bl][col]        + s_xp[cur][bl][col];
            float zf = s_z[bl][64 + col]   + s_xp[cur][bl][64 + col];
            float zg = s_z[bl][128 + col]  + s_xp[cur][bl][128 + col];
            float zo = s_z[bl][192 + col]  + s_xp[cur][bl][192 + col];
            float c  = sigm_mufu(zf) * s_c[bl][col] + sigm_mufu(zi) * tanh_mufu(zg);
            s_c[bl][col] = c;
            float h  = sigm_mufu(zo) * tanh_mufu(c);
            s_out[cur][bl][col] = h;
            if (t == Tt - 1)
                g_hf[(cl * 2 + bl) * Hh + j * 64 + col] = h;

            asm volatile("bar.sync 2, 128;" ::: "memory");

            if (t < Tt - 1 && tid < 4) {
                asm volatile("fence.proxy.async.shared::cta;" ::: "memory");
                const int p = tid;
                uint32_t src  = s_out_addr + (uint32_t)(cur * 512);
                uint32_t ldst = s_h_addr + (uint32_t)(nxt * PAR_STRIDE + j * J_STRIDE);
                uint32_t lmb  = mbar_addr + (uint32_t)nxt * 8;
                uint32_t rd, rm;
                asm("mapa.shared::cluster.u32 %0, %1, %2;" : "=r"(rd) : "r"(ldst), "r"(p));
                asm("mapa.shared::cluster.u32 %0, %1, %2;" : "=r"(rm) : "r"(lmb), "r"(p));
                asm volatile(
                    "cp.async.bulk.shared::cluster.shared::cta.mbarrier::complete_tx::bytes "
                    "[%0], [%1], %2, [%3];"
                    :: "r"(rd), "r"(src), "r"(512), "r"(rm) : "memory");
            }
        } else {
            // FMA-only warps: signal s_z done, go straight to next wait.
            asm volatile("bar.arrive 1, 512;" ::: "memory");
        }
    }
}

// =====================================================================
// Kernel 3: backward LSTM (single step, h=c=0) + fc1(relu) + fc2
// =====================================================================
__global__ __launch_bounds__(256) void head_kernel(
    const int* __restrict__ x,
    const float* __restrict__ emb,
    const float* __restrict__ wihb,
    const float* __restrict__ bihb,
    const float* __restrict__ bhhb,
    const float* __restrict__ fc1w,
    const float* __restrict__ fc1b,
    const float* __restrict__ fc2w,
    const float* __restrict__ fc2b,
    float* __restrict__ out)
{
    __shared__ __align__(16) float s_e[Ee];
    __shared__ float s_lo[2 * Hh];
    __shared__ float s_f1[24];

    const int b = blockIdx.x;
    const int tid = threadIdx.x;

    const int tok = x[b * Tt + (Tt - 1)];
    s_e[tid]  = emb[(size_t)tok * Ee + tid];
    s_lo[tid] = g_hf[b * Hh + tid];
    __syncthreads();

    float zi = bihb[tid]       + bhhb[tid];
    float zg = bihb[512 + tid] + bhhb[512 + tid];
    float zo = bihb[768 + tid] + bhhb[768 + tid];
    const float4* wi = (const float4*)(wihb + (size_t)tid * Ee);
    const float4* wg = (const float4*)(wihb + (size_t)(512 + tid) * Ee);
    const float4* wo = (const float4*)(wihb + (size_t)(768 + tid) * Ee);
    const float4* ev = (const float4*)s_e;
#pragma unroll 4
    for (int q = 0; q < Ee / 4; q++) {
        float4 e4 = ev[q];
        float4 vi = wi[q], vg = wg[q], vo = wo[q];
        zi += vi.x * e4.x + vi.y * e4.y + vi.z * e4.z + vi.w * e4.w;
        zg += vg.x * e4.x + vg.y * e4.y + vg.z * e4.z + vg.w * e4.w;
        zo += vo.x * e4.x + vo.y * e4.y + vo.z * e4.z + vo.w * e4.w;
    }
    float c = sigm(zi) * tanhf(zg);   // c_prev = 0: forget gate drops out
    float h = sigm(zo) * tanhf(c);
    s_lo[Hh + tid] = h;
    __syncthreads();

    if (tid < 24) {
        float s = fc1b[tid];
        const float* w = fc1w + (size_t)tid * (2 * Hh);
#pragma unroll 8
        for (int k = 0; k < 2 * Hh; k++) s = fmaf(w[k], s_lo[k], s);
        s_f1[tid] = fmaxf(s, 0.0f);
    }
    __syncthreads();
    if (tid < Oo) {
        float s = fc2b[tid];
        const float* w = fc2w + (size_t)tid * 24;
#pragma unroll
        for (int k = 0; k < 24; k++) s = fmaf(w[k], s_f1[k], s);
        out[b * Oo + tid] = s;
    }
}

// no-op pad launches: aim the ncu capture slot at the lstm kernel
__global__ void pad_kernel() {}

// =====================================================================
// launch
// =====================================================================
extern "C" void kernel_launch(void* const* d_in, const int* in_sizes, int n_in,
                              void* d_out, int out_size)
{
    const int* x           = (const int*)d_in[0];
    const float* emb       = (const float*)d_in[1];
    const float* w_ih_f    = (const float*)d_in[2];
    const float* w_hh_f    = (const float*)d_in[3];
    const float* b_ih_f    = (const float*)d_in[4];
    const float* b_hh_f    = (const float*)d_in[5];
    const float* w_ih_b    = (const float*)d_in[6];
    // d_in[7] = w_hh_b (unused: backward dir is a single step from h=0)
    const float* b_ih_b    = (const float*)d_in[8];
    const float* b_hh_b    = (const float*)d_in[9];
    const float* fc1_w     = (const float*)d_in[10];
    const float* fc1_b     = (const float*)d_in[11];
    const float* fc2_w     = (const float*)d_in[12];
    const float* fc2_b     = (const float*)d_in[13];
    float* out             = (float*)d_out;

    static bool attr_set = false;
    if (!attr_set) {
        cudaFuncSetAttribute(xproj_mma_kernel,
                             cudaFuncAttributeMaxDynamicSharedMemorySize, XSMEM_BYTES);
        attr_set = true;
    }

    dim3 xgrid(Tt * Bb / XBM, G4 / XBN);   // (256, 8)
    xproj_mma_kernel<<<xgrid, 256, XSMEM_BYTES>>>(x, emb, w_ih_f, b_ih_f, b_hh_f);

    pad_kernel<<<1, 32>>>();
    pad_kernel<<<1, 32>>>();

    lstm_fwd_kernel<<<128, 512>>>(w_hh_f);

    head_kernel<<<Bb, 256>>>(x, emb, w_ih_b, b_ih_b, b_hh_b,
                             fc1_w, fc1_b, fc2_w, fc2_b, out);
}